// round 9
// baseline (speedup 1.0000x reference)
#include <cuda_runtime.h>
#include <math.h>
#include <stdint.h>

#define EMBED 256
#define BATCH 32
#define TQ 1024
#define TKV 512
#define NMELS_R 320
#define NLAYERS 4
#define SQRT_HALF 0.70710678118654752440f

// ---------------- scratch (device globals; no allocation allowed) ----------------
__device__ float g_h   [BATCH * TQ * EMBED];
__device__ float g_h2  [BATCH * TQ * EMBED];
__device__ float g_ctx [BATCH * TQ * EMBED];
__device__ float g_qin [BATCH * TQ * EMBED];
__device__ float g_kin [BATCH * TKV * EMBED];
__device__ float g_kout[BATCH * TKV * EMBED];
__device__ float g_vout[BATCH * TKV * EMBED];
__device__ float g_big [BATCH * TQ * 512];
__device__ float g_peq [TQ * EMBED];
__device__ float g_pek [TKV * EMBED];

// ---------------- positional encoding (VERIFIED R5 @5.5e-7 — DO NOT CHANGE) ----------------
__global__ void posenc_kernel(float* __restrict__ pe, int T, float rate) {
    int idx = blockIdx.x * blockDim.x + threadIdx.x;
    if (idx >= T * EMBED) return;
    int t = idx / EMBED;
    int c = idx - t * EMBED;
    double e = (double)(2.0f * (float)(c >> 1) / 256.0f);
    float power = (float)pow(10000.0, e);
    float recip = 1.0f / power;
    float p  = (float)t;
    float t1 = p * rate;
    float t2 = t1 * recip;
    float angle = p * t2;
    double a = (double)angle;
    pe[idx] = (c & 1) ? (float)cos(a) : (float)sin(a);
}

__global__ void addpe_kernel(const float* __restrict__ x, const float* __restrict__ pe,
                             float* __restrict__ y, int period) {
    long long idx = (long long)blockIdx.x * blockDim.x + threadIdx.x;
    long long r = idx >> 8;
    int c = (int)(idx & 255);
    int t = (int)(r & (period - 1));
    y[idx] = x[idx] + pe[t * EMBED + c];
}

// ---------------- TF32 tensor-core GEMM, pre-split (hi,lo) smem, reg double-buffer ----------------
enum AMode { A_NORMAL = 0, A_CONV = 2 };
enum Epi   { E_RELU = 0, E_BIAS = 1, E_NONE = 2, E_SCALE = 3, E_RESID = 4 };

// smem (floats): As[2][128][40] interleaved (hi@2k, lo@2k+1), Bs[2][16][264] interleaved (hi@2n, lo@2n+1)
#define AS_STRIDE 40
#define BS_STRIDE 264
#define AS_BUF (128 * AS_STRIDE)
#define BS_BUF (16 * BS_STRIDE)
#define GSMEM_FLOATS (2 * AS_BUF + 2 * BS_BUF)
#define GSMEM_BYTES (GSMEM_FLOATS * 4)   // 74752

__device__ __forceinline__ void split2(float x, float& hi, float& lo) {
    asm("cvt.rna.tf32.f32 %0, %1;" : "=f"(hi) : "f"(x));
    float d = x - hi;
    asm("cvt.rna.tf32.f32 %0, %1;" : "=f"(lo) : "f"(d));
}
__device__ __forceinline__ void mma_tf32(float* c, const uint32_t* a, const uint32_t* b) {
    asm volatile(
        "mma.sync.aligned.m16n8k8.row.col.f32.tf32.tf32.f32 "
        "{%0,%1,%2,%3}, {%4,%5,%6,%7}, {%8,%9}, {%0,%1,%2,%3};"
        : "+f"(c[0]), "+f"(c[1]), "+f"(c[2]), "+f"(c[3])
        : "r"(a[0]), "r"(a[1]), "r"(a[2]), "r"(a[3]), "r"(b[0]), "r"(b[1]));
}

// C[M,N] = epi( A[M,K] @ B[K,N] );  TRANSB: B stored [N,K].
// 128x128x16 CTA tile, 8 warps (2x4), warp tile 64x32 via 4x4 m16n8k8, 3xTF32 split.
// A_CONV: row r -> (b=r>>10, t=r&1023); k = tap*256+ci gathers h[b, t-(4-tap)*dil, ci].
template<int AMODE, bool TRANSB, int EPI>
__global__ void __launch_bounds__(256, 1)
gemm_kernel(const float* __restrict__ A, const float* __restrict__ Bm,
            float* __restrict__ C,
            const float* __restrict__ bias,
            const float* __restrict__ resid,
            int M, int N, int K,
            long long sA, long long sB, long long sC,
            int dil, float scale)
{
    extern __shared__ float sm[];
    float* As = sm;                     // [2][128][40]
    float* Bs = sm + 2 * AS_BUF;        // [2][16][264]

    const int bz = blockIdx.z;
    A  += bz * sA;
    Bm += bz * sB;
    C  += bz * sC;

    const int row0 = blockIdx.y * 128;
    const int col0 = blockIdx.x * 128;
    const int tid  = threadIdx.x;
    const int lane = tid & 31;
    const int warp = tid >> 5;
    const int wm = warp >> 2;
    const int wn = warp & 3;
    const int m0 = wm * 64;
    const int n0 = wn * 32;
    const int g = lane >> 2;
    const int t = lane & 3;

    const int nk = K / 16;
    const int a_r  = tid >> 1;
    const int a_kc = (tid & 1) * 8;

    float4 ra[2], rb[2];

    auto ldgA = [&](int kt) {
#pragma unroll
        for (int u = 0; u < 2; u++) {
            const int kg = kt * 16 + a_kc + u * 4;
            const int gr = row0 + a_r;
            if (AMODE == A_CONV) {
                const int tap = kg >> 8;
                const int ci  = kg & 255;
                const int shift = (4 - tap) * dil;
                const int b_ = gr >> 10;
                const int t_ = gr & 1023;
                ra[u] = (t_ >= shift)
                    ? *(const float4*)&A[((size_t)((b_ << 10) + (t_ - shift))) * EMBED + ci]
                    : make_float4(0.f, 0.f, 0.f, 0.f);
            } else {
                ra[u] = *(const float4*)&A[(size_t)gr * K + kg];
            }
        }
    };
    auto ldgB = [&](int kt) {
#pragma unroll
        for (int u = 0; u < 2; u++) {
            const int slot = tid + u * 256;
            if (!TRANSB) {
                const int kk = slot >> 5;
                const int nc = (slot & 31) * 4;
                const int gn = col0 + nc;
                rb[u] = (gn < N) ? *(const float4*)&Bm[(size_t)(kt * 16 + kk) * N + gn]
                                 : make_float4(0.f, 0.f, 0.f, 0.f);
            } else {
                const int n  = slot >> 2;
                const int kc = (slot & 3) * 4;
                const int gn = col0 + n;
                rb[u] = (gn < N) ? *(const float4*)&Bm[(size_t)gn * K + kt * 16 + kc]
                                 : make_float4(0.f, 0.f, 0.f, 0.f);
            }
        }
    };
    auto stsA = [&](int b) {
        float* dst = As + b * AS_BUF + a_r * AS_STRIDE;
#pragma unroll
        for (int u = 0; u < 2; u++) {
            float h0, l0, h1, l1, h2, l2, h3, l3;
            split2(ra[u].x, h0, l0); split2(ra[u].y, h1, l1);
            split2(ra[u].z, h2, l2); split2(ra[u].w, h3, l3);
            const int k = a_kc + u * 4;
            *(float4*)&dst[2 * k]     = make_float4(h0, l0, h1, l1);
            *(float4*)&dst[2 * k + 4] = make_float4(h2, l2, h3, l3);
        }
    };
    auto stsB = [&](int b) {
        float* base = Bs + b * BS_BUF;
#pragma unroll
        for (int u = 0; u < 2; u++) {
            const int slot = tid + u * 256;
            if (!TRANSB) {
                const int kk = slot >> 5;
                const int nc = (slot & 31) * 4;
                float h0, l0, h1, l1, h2, l2, h3, l3;
                split2(rb[u].x, h0, l0); split2(rb[u].y, h1, l1);
                split2(rb[u].z, h2, l2); split2(rb[u].w, h3, l3);
                float* d = base + kk * BS_STRIDE + 2 * nc;
                *(float4*)&d[0] = make_float4(h0, l0, h1, l1);
                *(float4*)&d[4] = make_float4(h2, l2, h3, l3);
            } else {
                const int n  = slot >> 2;
                const int kc = (slot & 3) * 4;
                const float x[4] = {rb[u].x, rb[u].y, rb[u].z, rb[u].w};
#pragma unroll
                for (int i2 = 0; i2 < 4; i2++) {
                    float h, l;
                    split2(x[i2], h, l);
                    *(float2*)&base[(kc + i2) * BS_STRIDE + 2 * n] = make_float2(h, l);
                }
            }
        }
    };

    float acc[4][4][4];
#pragma unroll
    for (int i = 0; i < 4; i++)
#pragma unroll
        for (int j = 0; j < 4; j++)
#pragma unroll
            for (int r = 0; r < 4; r++) acc[i][j][r] = 0.0f;

    // prologue
    ldgA(0); ldgB(0);
    stsA(0); stsB(0);
    __syncthreads();

    for (int kt = 0; kt < nk; kt++) {
        const int cur = kt & 1;
        const int nxt = cur ^ 1;
        const bool more = (kt + 1 < nk);

        if (more) { ldgA(kt + 1); ldgB(kt + 1); }

        const float* Ab = As + cur * AS_BUF;
        const float* Bb = Bs + cur * BS_BUF;

#pragma unroll
        for (int step = 0; step < 2; step++) {
            const int kk = step * 8;
            uint32_t ahi[4][4], alo[4][4], bhi[4][2], blo[4][2];
#pragma unroll
            for (int i = 0; i < 4; i++) {
                const int r = m0 + i * 16 + g;
                const float2 p0 = *(const float2*)&Ab[r * AS_STRIDE + 2 * (kk + t)];
                const float2 p1 = *(const float2*)&Ab[(r + 8) * AS_STRIDE + 2 * (kk + t)];
                const float2 p2 = *(const float2*)&Ab[r * AS_STRIDE + 2 * (kk + t + 4)];
                const float2 p3 = *(const float2*)&Ab[(r + 8) * AS_STRIDE + 2 * (kk + t + 4)];
                ahi[i][0] = __float_as_uint(p0.x); alo[i][0] = __float_as_uint(p0.y);
                ahi[i][1] = __float_as_uint(p1.x); alo[i][1] = __float_as_uint(p1.y);
                ahi[i][2] = __float_as_uint(p2.x); alo[i][2] = __float_as_uint(p2.y);
                ahi[i][3] = __float_as_uint(p3.x); alo[i][3] = __float_as_uint(p3.y);
            }
#pragma unroll
            for (int j = 0; j < 4; j++) {
                const int n = n0 + j * 8 + g;
                const float2 q0 = *(const float2*)&Bb[(kk + t) * BS_STRIDE + 2 * n];
                const float2 q1 = *(const float2*)&Bb[(kk + t + 4) * BS_STRIDE + 2 * n];
                bhi[j][0] = __float_as_uint(q0.x); blo[j][0] = __float_as_uint(q0.y);
                bhi[j][1] = __float_as_uint(q1.x); blo[j][1] = __float_as_uint(q1.y);
            }
#pragma unroll
            for (int i = 0; i < 4; i++)
#pragma unroll
                for (int j = 0; j < 4; j++) {
                    mma_tf32(acc[i][j], ahi[i], bhi[j]);
                    mma_tf32(acc[i][j], alo[i], bhi[j]);
                    mma_tf32(acc[i][j], ahi[i], blo[j]);
                }
        }

        if (more) { stsA(nxt); stsB(nxt); }
        __syncthreads();
    }

    // ---- epilogue: c0/c1 = (row, col..col+1), c2/c3 = (row+8, col..col+1) ----
#pragma unroll
    for (int i = 0; i < 4; i++) {
#pragma unroll
        for (int j = 0; j < 4; j++) {
            const int cc = col0 + n0 + j * 8 + t * 2;
            if (cc >= N) continue;
#pragma unroll
            for (int half = 0; half < 2; half++) {
                const int r = row0 + m0 + i * 16 + g + half * 8;
                float v0 = acc[i][j][half * 2 + 0];
                float v1 = acc[i][j][half * 2 + 1];
                if (EPI == E_RELU)  { v0 = fmaxf(v0 + bias[cc], 0.0f); v1 = fmaxf(v1 + bias[cc + 1], 0.0f); }
                if (EPI == E_BIAS)  { v0 += bias[cc]; v1 += bias[cc + 1]; }
                if (EPI == E_SCALE) { v0 *= scale; v1 *= scale; }
                if (EPI == E_RESID) {
                    const float2 rs = *(const float2*)&resid[(size_t)r * N + cc];
                    v0 = (v0 + bias[cc]     + rs.x) * SQRT_HALF;
                    v1 = (v1 + bias[cc + 1] + rs.y) * SQRT_HALF;
                }
                *(float2*)&C[(size_t)r * N + cc] = make_float2(v0, v1);
            }
        }
    }
}

// ---------------- GLU + residual + fused q-input ----------------
__global__ void glu_kernel(const float* __restrict__ y, float* __restrict__ h,
                           float* __restrict__ qin, const float* __restrict__ peq) {
    long long idx = (long long)blockIdx.x * blockDim.x + threadIdx.x;
    if (idx >= (long long)BATCH * TQ * EMBED) return;
    long long r = idx >> 8;
    int c = (int)(idx & 255);
    int t = (int)(r & 1023);
    float a = y[r * 512 + c];
    float g = y[r * 512 + 256 + c];
    float s = 1.0f / (1.0f + expf(-g));
    float hv = (h[idx] + a * s) * SQRT_HALF;
    h[idx] = hv;
    qin[idx] = hv + peq[t * EMBED + c];
}

// ---------------- row softmax over 512 ----------------
__global__ void softmax_kernel(float* __restrict__ x) {
    __shared__ float red[128];
    float* p = x + (long long)blockIdx.x * 512;
    const int tid = threadIdx.x;
    float v[4];
    float m = -1e30f;
#pragma unroll
    for (int i = 0; i < 4; i++) { v[i] = p[tid + i * 128]; m = fmaxf(m, v[i]); }
    red[tid] = m; __syncthreads();
#pragma unroll
    for (int s = 64; s > 0; s >>= 1) {
        if (tid < s) red[tid] = fmaxf(red[tid], red[tid + s]);
        __syncthreads();
    }
    m = red[0];
    __syncthreads();
    float sum = 0.0f;
#pragma unroll
    for (int i = 0; i < 4; i++) { v[i] = expf(v[i] - m); sum += v[i]; }
    red[tid] = sum; __syncthreads();
#pragma unroll
    for (int s = 64; s > 0; s >>= 1) {
        if (tid < s) red[tid] += red[tid + s];
        __syncthreads();
    }
    float inv = 1.0f / red[0];
#pragma unroll
    for (int i = 0; i < 4; i++) p[tid + i * 128] = v[i] * inv;
}

// ---------------- done head ----------------
__global__ void done_kernel(const float* __restrict__ h, const float* __restrict__ w,
                            const float* __restrict__ b, float* __restrict__ out) {
    const int row  = blockIdx.x * 8 + (threadIdx.x >> 5);
    const int lane = threadIdx.x & 31;
    if (row >= BATCH * TQ) return;
    const float* hr = h + (long long)row * EMBED;
    float s0 = 0.0f, s1 = 0.0f;
    for (int k = lane; k < EMBED; k += 32) {
        float hv = hr[k];
        s0 = fmaf(hv, w[k * 2 + 0], s0);
        s1 = fmaf(hv, w[k * 2 + 1], s1);
    }
#pragma unroll
    for (int o = 16; o > 0; o >>= 1) {
        s0 += __shfl_down_sync(0xffffffffu, s0, o);
        s1 += __shfl_down_sync(0xffffffffu, s1, o);
    }
    if (lane == 0) {
        out[row * 2 + 0] = 1.0f / (1.0f + expf(-(s0 + b[0])));
        out[row * 2 + 1] = 1.0f / (1.0f + expf(-(s1 + b[1])));
    }
}

// ---------------- host orchestration ----------------
static inline dim3 gemm_grid(int M, int N, int z) {
    return dim3((N + 127) / 128, (M + 127) / 128, z);
}

extern "C" void kernel_launch(void* const* d_in, const int* in_sizes, int n_in,
                              void* d_out, int out_size) {
    const float* inputs  = (const float*)d_in[0];
    const float* keys    = (const float*)d_in[1];
    const float* values  = (const float*)d_in[2];
    const float* w_first = (const float*)d_in[3];
    const float* b_first = (const float*)d_in[4];
    const float* fc_w    = (const float*)d_in[5];
    const float* fc_b    = (const float*)d_in[6];
    const float* conv_w  = (const float*)d_in[7];
    const float* conv_b  = (const float*)d_in[8];
    const float* att_w1  = (const float*)d_in[9];
    const float* att_b1  = (const float*)d_in[10];
    const float* att_w2  = (const float*)d_in[11];
    const float* att_b2  = (const float*)d_in[12];
    const float* att_w3  = (const float*)d_in[13];
    const float* att_b3  = (const float*)d_in[14];
    const float* att_wo  = (const float*)d_in[15];
    const float* att_bo  = (const float*)d_in[16];
    const float* w_done  = (const float*)d_in[17];
    const float* b_done  = (const float*)d_in[18];
    const float* w_mel   = (const float*)d_in[19];
    const float* b_mel   = (const float*)d_in[20];

    float* out      = (float*)d_out;
    float* out_mel  = out;
    float* out_done = out + (long long)BATCH * TQ * NMELS_R;
    float* out_h    = out_done + (long long)BATCH * TQ * 2;

    float *h, *h2, *ctx, *qin, *kin, *kout, *vout, *big, *peq, *pek;
    cudaGetSymbolAddress((void**)&h,    g_h);
    cudaGetSymbolAddress((void**)&h2,   g_h2);
    cudaGetSymbolAddress((void**)&ctx,  g_ctx);
    cudaGetSymbolAddress((void**)&qin,  g_qin);
    cudaGetSymbolAddress((void**)&kin,  g_kin);
    cudaGetSymbolAddress((void**)&kout, g_kout);
    cudaGetSymbolAddress((void**)&vout, g_vout);
    cudaGetSymbolAddress((void**)&big,  g_big);
    cudaGetSymbolAddress((void**)&peq,  g_peq);
    cudaGetSymbolAddress((void**)&pek,  g_pek);

    // opt-in dynamic smem for every instantiation
    cudaFuncSetAttribute(gemm_kernel<A_NORMAL, false, E_RELU>,  cudaFuncAttributeMaxDynamicSharedMemorySize, GSMEM_BYTES);
    cudaFuncSetAttribute(gemm_kernel<A_NORMAL, false, E_BIAS>,  cudaFuncAttributeMaxDynamicSharedMemorySize, GSMEM_BYTES);
    cudaFuncSetAttribute(gemm_kernel<A_CONV,   false, E_BIAS>,  cudaFuncAttributeMaxDynamicSharedMemorySize, GSMEM_BYTES);
    cudaFuncSetAttribute(gemm_kernel<A_NORMAL, true,  E_NONE>,  cudaFuncAttributeMaxDynamicSharedMemorySize, GSMEM_BYTES);
    cudaFuncSetAttribute(gemm_kernel<A_NORMAL, false, E_SCALE>, cudaFuncAttributeMaxDynamicSharedMemorySize, GSMEM_BYTES);
    cudaFuncSetAttribute(gemm_kernel<A_NORMAL, false, E_RESID>, cudaFuncAttributeMaxDynamicSharedMemorySize, GSMEM_BYTES);

    const int M  = BATCH * TQ;    // 32768
    const int Mk = BATCH * TKV;   // 16384
    const float rsqrt_tk = 1.0f / sqrtf((float)TKV);

    posenc_kernel<<<(TQ * EMBED + 255) / 256, 256>>>(peq, TQ, 1.0f);
    posenc_kernel<<<(TKV * EMBED + 255) / 256, 256>>>(pek, TKV, 2.0f);
    addpe_kernel<<<(Mk * EMBED + 255) / 256, 256>>>(keys, pek, kin, TKV);

    gemm_kernel<A_NORMAL, false, E_RELU><<<gemm_grid(M, EMBED, 1), 256, GSMEM_BYTES>>>(
        inputs, w_first, h2, b_first, nullptr,
        M, EMBED, NMELS_R, 0, 0, 0, 0, 0.0f);
    gemm_kernel<A_NORMAL, false, E_RELU><<<gemm_grid(M, EMBED, 1), 256, GSMEM_BYTES>>>(
        h2, fc_w + 0 * EMBED * EMBED, h, fc_b + 0 * EMBED, nullptr,
        M, EMBED, EMBED, 0, 0, 0, 0, 0.0f);
    gemm_kernel<A_NORMAL, false, E_RELU><<<gemm_grid(M, EMBED, 1), 256, GSMEM_BYTES>>>(
        h, fc_w + 1 * EMBED * EMBED, h2, fc_b + 1 * EMBED, nullptr,
        M, EMBED, EMBED, 0, 0, 0, 0, 0.0f);
    gemm_kernel<A_NORMAL, false, E_RELU><<<gemm_grid(M, EMBED, 1), 256, GSMEM_BYTES>>>(
        h2, fc_w + 2 * EMBED * EMBED, h, fc_b + 2 * EMBED, nullptr,
        M, EMBED, EMBED, 0, 0, 0, 0, 0.0f);

    for (int i = 0; i < NLAYERS; i++) {
        const int dil = 1 << i;
        gemm_kernel<A_CONV, false, E_BIAS><<<gemm_grid(M, 512, 1), 256, GSMEM_BYTES>>>(
            h, conv_w + (long long)i * 5 * EMBED * 512, big,
            conv_b + i * 512, nullptr,
            M, 512, 5 * EMBED, 0, 0, 0, dil, 0.0f);
        glu_kernel<<<(M * EMBED + 255) / 256, 256>>>(big, h, qin, peq);

        gemm_kernel<A_NORMAL, false, E_BIAS><<<gemm_grid(M, EMBED, 1), 256, GSMEM_BYTES>>>(
            qin, att_w2 + (long long)i * EMBED * EMBED, h2,
            att_b2 + i * EMBED, nullptr,
            M, EMBED, EMBED, 0, 0, 0, 0, 0.0f);
        gemm_kernel<A_NORMAL, false, E_BIAS><<<gemm_grid(Mk, EMBED, 1), 256, GSMEM_BYTES>>>(
            kin, att_w1 + (long long)i * EMBED * EMBED, kout,
            att_b1 + i * EMBED, nullptr,
            Mk, EMBED, EMBED, 0, 0, 0, 0, 0.0f);
        gemm_kernel<A_NORMAL, false, E_BIAS><<<gemm_grid(Mk, EMBED, 1), 256, GSMEM_BYTES>>>(
            values, att_w3 + (long long)i * EMBED * EMBED, vout,
            att_b3 + i * EMBED, nullptr,
            Mk, EMBED, EMBED, 0, 0, 0, 0, 0.0f);

        gemm_kernel<A_NORMAL, true, E_NONE><<<gemm_grid(TQ, TKV, BATCH), 256, GSMEM_BYTES>>>(
            h2, kout, big, nullptr, nullptr,
            TQ, TKV, EMBED,
            (long long)TQ * EMBED, (long long)TKV * EMBED, (long long)TQ * TKV,
            0, 0.0f);
        softmax_kernel<<<M, 128>>>(big);
        gemm_kernel<A_NORMAL, false, E_SCALE><<<gemm_grid(TQ, EMBED, BATCH), 256, GSMEM_BYTES>>>(
            big, vout, ctx, nullptr, nullptr,
            TQ, EMBED, TKV,
            (long long)TQ * TKV, (long long)TKV * EMBED, (long long)TQ * EMBED,
            0, rsqrt_tk);
        gemm_kernel<A_NORMAL, false, E_RESID><<<gemm_grid(M, EMBED, 1), 256, GSMEM_BYTES>>>(
            ctx, att_wo + (long long)i * EMBED * EMBED, h,
            att_bo + i * EMBED, h,
            M, EMBED, EMBED, 0, 0, 0, 0, 0.0f);
    }

    gemm_kernel<A_NORMAL, false, E_BIAS><<<gemm_grid(M, NMELS_R, 1), 256, GSMEM_BYTES>>>(
        h, w_mel, out_mel, b_mel, nullptr,
        M, NMELS_R, EMBED, 0, 0, 0, 0, 0.0f);
    done_kernel<<<(M + 7) / 8, 256>>>(h, w_done, b_done, out_done);
    cudaMemcpyAsync(out_h, h, sizeof(float) * (size_t)M * EMBED,
                    cudaMemcpyDeviceToDevice);
}

// round 10
// speedup vs baseline: 1.1588x; 1.1588x over previous
#include <cuda_runtime.h>
#include <math.h>
#include <stdint.h>

#define EMBED 256
#define BATCH 32
#define TQ 1024
#define TKV 512
#define NMELS_R 320
#define NLAYERS 4
#define SQRT_HALF 0.70710678118654752440f

// ---------------- scratch (device globals; no allocation allowed) ----------------
// f32 tensors
__device__ float g_h   [BATCH * TQ * EMBED];     // hidden state (f32 view)
__device__ float g_big [BATCH * TQ * 512];       // conv out / raw scores (f32)
__device__ float g_peq [TQ * EMBED];
__device__ float g_pek [TKV * EMBED];
// pre-split (hi,lo) pairs — operands of GEMMs
__device__ float g_inh [BATCH * TQ * NMELS_R];
__device__ float g_inl [BATCH * TQ * NMELS_R];
__device__ float g_valh[BATCH * TKV * EMBED];
__device__ float g_vall[BATCH * TKV * EMBED];
__device__ float g_wfh [NMELS_R * EMBED];
__device__ float g_wfl [NMELS_R * EMBED];
__device__ float g_fcwh[3 * EMBED * EMBED];
__device__ float g_fcwl[3 * EMBED * EMBED];
__device__ float g_cwh [NLAYERS * 5 * EMBED * 512];
__device__ float g_cwl [NLAYERS * 5 * EMBED * 512];
__device__ float g_w1h [NLAYERS * EMBED * EMBED];
__device__ float g_w1l [NLAYERS * EMBED * EMBED];
__device__ float g_w2h [NLAYERS * EMBED * EMBED];
__device__ float g_w2l [NLAYERS * EMBED * EMBED];
__device__ float g_w3h [NLAYERS * EMBED * EMBED];
__device__ float g_w3l [NLAYERS * EMBED * EMBED];
__device__ float g_woh [NLAYERS * EMBED * EMBED];
__device__ float g_wol [NLAYERS * EMBED * EMBED];
__device__ float g_mwh [EMBED * NMELS_R];
__device__ float g_mwl [EMBED * NMELS_R];
// split activations
__device__ float g_hh  [BATCH * TQ * EMBED];
__device__ float g_hl  [BATCH * TQ * EMBED];
__device__ float g_h2h [BATCH * TQ * EMBED];
__device__ float g_h2l [BATCH * TQ * EMBED];
__device__ float g_qinh[BATCH * TQ * EMBED];
__device__ float g_qinl[BATCH * TQ * EMBED];
__device__ float g_kinh[BATCH * TKV * EMBED];
__device__ float g_kinl[BATCH * TKV * EMBED];
__device__ float g_koh [BATCH * TKV * EMBED];
__device__ float g_kol [BATCH * TKV * EMBED];
__device__ float g_voh [BATCH * TKV * EMBED];
__device__ float g_vol [BATCH * TKV * EMBED];
__device__ float g_bh  [BATCH * TQ * 512];
__device__ float g_bl  [BATCH * TQ * 512];
__device__ float g_cxh [BATCH * TQ * EMBED];
__device__ float g_cxl [BATCH * TQ * EMBED];

// ---------------- low-level helpers ----------------
__device__ __forceinline__ uint32_t smem_u32(const void* p) {
    return (uint32_t)__cvta_generic_to_shared(p);
}
__device__ __forceinline__ void cp_async16(uint32_t dst, const void* src, int src_bytes) {
    asm volatile("cp.async.cg.shared.global [%0], [%1], 16, %2;\n"
                 :: "r"(dst), "l"(src), "r"(src_bytes));
}
__device__ __forceinline__ void cp_async_commit() { asm volatile("cp.async.commit_group;\n"); }
__device__ __forceinline__ void cp_async_wait0()  { asm volatile("cp.async.wait_group 0;\n"); }

__device__ __forceinline__ void split2(float x, float& hi, float& lo) {
    asm("cvt.rna.tf32.f32 %0, %1;" : "=f"(hi) : "f"(x));
    float d = x - hi;
    asm("cvt.rna.tf32.f32 %0, %1;" : "=f"(lo) : "f"(d));
}
__device__ __forceinline__ void mma_tf32(float* c, const uint32_t* a, const uint32_t* b) {
    asm volatile(
        "mma.sync.aligned.m16n8k8.row.col.f32.tf32.tf32.f32 "
        "{%0,%1,%2,%3}, {%4,%5,%6,%7}, {%8,%9}, {%0,%1,%2,%3};"
        : "+f"(c[0]), "+f"(c[1]), "+f"(c[2]), "+f"(c[3])
        : "r"(a[0]), "r"(a[1]), "r"(a[2]), "r"(a[3]), "r"(b[0]), "r"(b[1]));
}

// ---------------- positional encoding (VERIFIED R5 @5.5e-7 — DO NOT CHANGE) ----------------
__global__ void posenc_kernel(float* __restrict__ pe, int T, float rate) {
    int idx = blockIdx.x * blockDim.x + threadIdx.x;
    if (idx >= T * EMBED) return;
    int t = idx / EMBED;
    int c = idx - t * EMBED;
    double e = (double)(2.0f * (float)(c >> 1) / 256.0f);
    float power = (float)pow(10000.0, e);
    float recip = 1.0f / power;
    float p  = (float)t;
    float t1 = p * rate;
    float t2 = t1 * recip;
    float angle = p * t2;
    double a = (double)angle;
    pe[idx] = (c & 1) ? (float)cos(a) : (float)sin(a);
}

// ---------------- elementwise split: (hi,lo) = split(x) ----------------
__global__ void split_kernel(const float* __restrict__ x,
                             float* __restrict__ hi, float* __restrict__ lo, int n) {
    int idx = blockIdx.x * blockDim.x + threadIdx.x;
    if (idx >= n) return;
    float h, l;
    split2(x[idx], h, l);
    hi[idx] = h; lo[idx] = l;
}

// kin = keys + pek, split
__global__ void addpe_kernel(const float* __restrict__ x, const float* __restrict__ pe,
                             float* __restrict__ yh, float* __restrict__ yl, int period) {
    long long idx = (long long)blockIdx.x * blockDim.x + threadIdx.x;
    long long r = idx >> 8;
    int c = (int)(idx & 255);
    int t = (int)(r & (period - 1));
    float h, l;
    split2(x[idx] + pe[t * EMBED + c], h, l);
    yh[idx] = h; yl[idx] = l;
}

// ---------------- TF32 GEMM: pre-split global operands, cp.async pipeline ----------------
enum AMode { A_NORMAL = 0, A_CONV = 2 };
enum Epi   { E_RELU = 0, E_BIAS = 1, E_NONE = 2, E_SCALE = 3, E_RESID = 4 };

// smem word offsets: Ah[2][128][20], Al[...], Bh[2][16][136], Bl[...]
#define A_BUF 2560
#define B_BUF 2176
#define AH_OFF 0
#define AL_OFF 5120
#define BH_OFF 10240
#define BL_OFF 14592
#define GSMEM_BYTES 75776

// C = epi( A @ B ); A,B given as hi/lo fp32 arrays. TRANSB: B stored [N][K].
// 128x128x16 CTA tile, 8 warps (2x4), warp 64x32, m16n8k8, 3xTF32 (hh, lh, hl).
template<int AMODE, bool TRANSB, int EPI, bool SPLITOUT, bool F32OUT>
__global__ void __launch_bounds__(256, 1)
gemm_kernel(const float* __restrict__ Ahi, const float* __restrict__ Alo,
            const float* __restrict__ Bhi, const float* __restrict__ Blo,
            float* __restrict__ C, float* __restrict__ Chi, float* __restrict__ Clo,
            const float* __restrict__ bias, const float* __restrict__ resid,
            int M, int N, int K,
            long long sA, long long sB, long long sC,
            int dil, float scale)
{
    extern __shared__ float sm[];
    const uint32_t sbase = smem_u32(sm);

    const int bz = blockIdx.z;
    Ahi += bz * sA;  Alo += bz * sA;
    Bhi += bz * sB;  Blo += bz * sB;
    if (F32OUT)   C   += bz * sC;
    if (SPLITOUT) { Chi += bz * sC; Clo += bz * sC; }

    const int row0 = blockIdx.y * 128;
    const int col0 = blockIdx.x * 128;
    const int tid  = threadIdx.x;
    const int lane = tid & 31;
    const int warp = tid >> 5;
    const int m0 = (warp >> 2) * 64;
    const int n0 = (warp & 3) * 32;
    const int g = lane >> 2;
    const int t = lane & 3;
    const int nk = K / 16;

    auto loadA = [&](int kt, int b) {
#pragma unroll
        for (int u = 0; u < 4; u++) {
            const int idx = tid + u * 256;           // 0..1023
            const int arr = idx >> 9;                // 0=hi 1=lo
            const int rem = idx & 511;
            const int r  = rem >> 2;
            const int kc = (rem & 3) * 4;
            const float* base = arr ? Alo : Ahi;
            const int kg = kt * 16 + kc;
            const int gr = row0 + r;
            const float* src; int sz = 16;
            if (AMODE == A_CONV) {
                const int tap = kg >> 8;
                const int ci  = kg & 255;
                const int shift = (4 - tap) * dil;
                const int b_ = gr >> 10;
                const int t_ = gr & 1023;
                if (t_ >= shift) src = base + ((size_t)((b_ << 10) + (t_ - shift))) * EMBED + ci;
                else { src = base; sz = 0; }
            } else {
                src = base + (size_t)gr * K + kg;
            }
            const uint32_t dst = sbase +
                (uint32_t)(((arr ? AL_OFF : AH_OFF) + b * A_BUF + r * 20 + kc) * 4);
            cp_async16(dst, src, sz);
        }
    };
    auto loadB = [&](int kt, int b) {
#pragma unroll
        for (int u = 0; u < 4; u++) {
            const int idx = tid + u * 256;
            const int arr = idx >> 9;
            const int rem = idx & 511;
            const int kk = rem >> 5;
            const int nc = (rem & 31) * 4;
            const int gn = col0 + nc;
            const float* base = arr ? Blo : Bhi;
            const float* src = base + (size_t)(kt * 16 + kk) * N + gn;
            int sz = 16;
            if (gn >= N) { src = base; sz = 0; }
            const uint32_t dst = sbase +
                (uint32_t)(((arr ? BL_OFF : BH_OFF) + b * B_BUF + kk * 136 + nc) * 4);
            cp_async16(dst, src, sz);
        }
    };
    float4 tb[4];
    auto ldgBt = [&](int kt) {
#pragma unroll
        for (int u = 0; u < 4; u++) {
            const int idx = tid + u * 256;
            const int arr = idx >> 9;
            const int rem = idx & 511;
            const int n  = rem >> 2;
            const int kc = (rem & 3) * 4;
            const int gn = col0 + n;
            const float* base = arr ? Blo : Bhi;
            tb[u] = (gn < N) ? *(const float4*)&base[(size_t)gn * K + kt * 16 + kc]
                             : make_float4(0.f, 0.f, 0.f, 0.f);
        }
    };
    auto stsBt = [&](int b) {
#pragma unroll
        for (int u = 0; u < 4; u++) {
            const int idx = tid + u * 256;
            const int arr = idx >> 9;
            const int rem = idx & 511;
            const int n  = rem >> 2;
            const int kc = (rem & 3) * 4;
            float* dstb = sm + (arr ? BL_OFF : BH_OFF) + b * B_BUF;
            dstb[(kc + 0) * 136 + n] = tb[u].x;
            dstb[(kc + 1) * 136 + n] = tb[u].y;
            dstb[(kc + 2) * 136 + n] = tb[u].z;
            dstb[(kc + 3) * 136 + n] = tb[u].w;
        }
    };

    float acc[4][4][4];
#pragma unroll
    for (int i = 0; i < 4; i++)
#pragma unroll
        for (int j = 0; j < 4; j++)
#pragma unroll
            for (int r = 0; r < 4; r++) acc[i][j][r] = 0.0f;

    // prologue
    loadA(0, 0);
    if (!TRANSB) {
        loadB(0, 0);
        cp_async_commit();
        cp_async_wait0();
    } else {
        cp_async_commit();
        ldgBt(0);
        cp_async_wait0();
        stsBt(0);
    }
    __syncthreads();

    for (int kt = 0; kt < nk; kt++) {
        const int cur = kt & 1;
        const int nxt = cur ^ 1;
        const bool more = (kt + 1 < nk);

        if (more) {
            loadA(kt + 1, nxt);
            if (!TRANSB) loadB(kt + 1, nxt);
            cp_async_commit();
            if (TRANSB) ldgBt(kt + 1);
        }

        const float* AH = sm + AH_OFF + cur * A_BUF;
        const float* AL = sm + AL_OFF + cur * A_BUF;
        const float* BH = sm + BH_OFF + cur * B_BUF;
        const float* BL = sm + BL_OFF + cur * B_BUF;

#pragma unroll
        for (int step = 0; step < 2; step++) {
            const int kk = step * 8;
            uint32_t ahi[4][4], alo[4][4], bhi[4][2], blo[4][2];
#pragma unroll
            for (int i = 0; i < 4; i++) {
                const int r = m0 + i * 16 + g;
                ahi[i][0] = __float_as_uint(AH[r * 20 + kk + t]);
                ahi[i][1] = __float_as_uint(AH[(r + 8) * 20 + kk + t]);
                ahi[i][2] = __float_as_uint(AH[r * 20 + kk + t + 4]);
                ahi[i][3] = __float_as_uint(AH[(r + 8) * 20 + kk + t + 4]);
                alo[i][0] = __float_as_uint(AL[r * 20 + kk + t]);
                alo[i][1] = __float_as_uint(AL[(r + 8) * 20 + kk + t]);
                alo[i][2] = __float_as_uint(AL[r * 20 + kk + t + 4]);
                alo[i][3] = __float_as_uint(AL[(r + 8) * 20 + kk + t + 4]);
            }
#pragma unroll
            for (int j = 0; j < 4; j++) {
                const int n = n0 + j * 8 + g;
                bhi[j][0] = __float_as_uint(BH[(kk + t) * 136 + n]);
                bhi[j][1] = __float_as_uint(BH[(kk + t + 4) * 136 + n]);
                blo[j][0] = __float_as_uint(BL[(kk + t) * 136 + n]);
                blo[j][1] = __float_as_uint(BL[(kk + t + 4) * 136 + n]);
            }
#pragma unroll
            for (int i = 0; i < 4; i++)
#pragma unroll
                for (int j = 0; j < 4; j++) {
                    mma_tf32(acc[i][j], ahi[i], bhi[j]);
                    mma_tf32(acc[i][j], alo[i], bhi[j]);
                    mma_tf32(acc[i][j], ahi[i], blo[j]);
                }
        }

        if (more && TRANSB) stsBt(nxt);
        cp_async_wait0();
        __syncthreads();
    }

    // ---- epilogue ----
#pragma unroll
    for (int i = 0; i < 4; i++) {
#pragma unroll
        for (int j = 0; j < 4; j++) {
            const int cc = col0 + n0 + j * 8 + t * 2;
            if (cc >= N) continue;
#pragma unroll
            for (int half = 0; half < 2; half++) {
                const int r = row0 + m0 + i * 16 + g + half * 8;
                float v0 = acc[i][j][half * 2 + 0];
                float v1 = acc[i][j][half * 2 + 1];
                if (EPI == E_RELU)  { v0 = fmaxf(v0 + bias[cc], 0.0f); v1 = fmaxf(v1 + bias[cc + 1], 0.0f); }
                if (EPI == E_BIAS)  { v0 += bias[cc]; v1 += bias[cc + 1]; }
                if (EPI == E_SCALE) { v0 *= scale; v1 *= scale; }
                if (EPI == E_RESID) {
                    const float2 rs = *(const float2*)&resid[(size_t)r * N + cc];
                    v0 = (v0 + bias[cc]     + rs.x) * SQRT_HALF;
                    v1 = (v1 + bias[cc + 1] + rs.y) * SQRT_HALF;
                }
                if (F32OUT)
                    *(float2*)&C[(size_t)r * N + cc] = make_float2(v0, v1);
                if (SPLITOUT) {
                    float h0, l0, h1, l1;
                    split2(v0, h0, l0);
                    split2(v1, h1, l1);
                    *(float2*)&Chi[(size_t)r * N + cc] = make_float2(h0, h1);
                    *(float2*)&Clo[(size_t)r * N + cc] = make_float2(l0, l1);
                }
            }
        }
    }
}

// ---------------- GLU + residual + fused split q-input ----------------
__global__ void glu_kernel(const float* __restrict__ y, float* __restrict__ h,
                           float* __restrict__ qh, float* __restrict__ ql,
                           const float* __restrict__ peq) {
    long long idx = (long long)blockIdx.x * blockDim.x + threadIdx.x;
    if (idx >= (long long)BATCH * TQ * EMBED) return;
    long long r = idx >> 8;
    int c = (int)(idx & 255);
    int t = (int)(r & 1023);
    float a = y[r * 512 + c];
    float g = y[r * 512 + 256 + c];
    float s = 1.0f / (1.0f + expf(-g));
    float hv = (h[idx] + a * s) * SQRT_HALF;
    h[idx] = hv;
    float sh, sl;
    split2(hv + peq[t * EMBED + c], sh, sl);
    qh[idx] = sh; ql[idx] = sl;
}

// ---------------- row softmax over 512, split output ----------------
__global__ void softmax_kernel(const float* __restrict__ x,
                               float* __restrict__ oh, float* __restrict__ ol) {
    __shared__ float red[128];
    const float* p = x + (long long)blockIdx.x * 512;
    const long long ob = (long long)blockIdx.x * 512;
    const int tid = threadIdx.x;
    float v[4];
    float m = -1e30f;
#pragma unroll
    for (int i = 0; i < 4; i++) { v[i] = p[tid + i * 128]; m = fmaxf(m, v[i]); }
    red[tid] = m; __syncthreads();
#pragma unroll
    for (int s = 64; s > 0; s >>= 1) {
        if (tid < s) red[tid] = fmaxf(red[tid], red[tid + s]);
        __syncthreads();
    }
    m = red[0];
    __syncthreads();
    float sum = 0.0f;
#pragma unroll
    for (int i = 0; i < 4; i++) { v[i] = expf(v[i] - m); sum += v[i]; }
    red[tid] = sum; __syncthreads();
#pragma unroll
    for (int s = 64; s > 0; s >>= 1) {
        if (tid < s) red[tid] += red[tid + s];
        __syncthreads();
    }
    float inv = 1.0f / red[0];
#pragma unroll
    for (int i = 0; i < 4; i++) {
        float sh, sl;
        split2(v[i] * inv, sh, sl);
        oh[ob + tid + i * 128] = sh;
        ol[ob + tid + i * 128] = sl;
    }
}

// ---------------- done head ----------------
__global__ void done_kernel(const float* __restrict__ h, const float* __restrict__ w,
                            const float* __restrict__ b, float* __restrict__ out) {
    const int row  = blockIdx.x * 8 + (threadIdx.x >> 5);
    const int lane = threadIdx.x & 31;
    if (row >= BATCH * TQ) return;
    const float* hr = h + (long long)row * EMBED;
    float s0 = 0.0f, s1 = 0.0f;
    for (int k = lane; k < EMBED; k += 32) {
        float hv = hr[k];
        s0 = fmaf(hv, w[k * 2 + 0], s0);
        s1 = fmaf(hv, w[k * 2 + 1], s1);
    }
#pragma unroll
    for (int o = 16; o > 0; o >>= 1) {
        s0 += __shfl_down_sync(0xffffffffu, s0, o);
        s1 += __shfl_down_sync(0xffffffffu, s1, o);
    }
    if (lane == 0) {
        out[row * 2 + 0] = 1.0f / (1.0f + expf(-(s0 + b[0])));
        out[row * 2 + 1] = 1.0f / (1.0f + expf(-(s1 + b[1])));
    }
}

// ---------------- host orchestration ----------------
static inline dim3 gemm_grid(int M, int N, int z) {
    return dim3((N + 127) / 128, (M + 127) / 128, z);
}
#define SYM(p, s) cudaGetSymbolAddress((void**)&p, s)

extern "C" void kernel_launch(void* const* d_in, const int* in_sizes, int n_in,
                              void* d_out, int out_size) {
    const float* inputs  = (const float*)d_in[0];
    const float* keys    = (const float*)d_in[1];
    const float* values  = (const float*)d_in[2];
    const float* w_first = (const float*)d_in[3];
    const float* b_first = (const float*)d_in[4];
    const float* fc_w    = (const float*)d_in[5];
    const float* fc_b    = (const float*)d_in[6];
    const float* conv_w  = (const float*)d_in[7];
    const float* conv_b  = (const float*)d_in[8];
    const float* att_w1  = (const float*)d_in[9];
    const float* att_b1  = (const float*)d_in[10];
    const float* att_w2  = (const float*)d_in[11];
    const float* att_b2  = (const float*)d_in[12];
    const float* att_w3  = (const float*)d_in[13];
    const float* att_b3  = (const float*)d_in[14];
    const float* att_wo  = (const float*)d_in[15];
    const float* att_bo  = (const float*)d_in[16];
    const float* w_done  = (const float*)d_in[17];
    const float* b_done  = (const float*)d_in[18];
    const float* w_mel   = (const float*)d_in[19];
    const float* b_mel   = (const float*)d_in[20];

    float* out      = (float*)d_out;
    float* out_mel  = out;
    float* out_done = out + (long long)BATCH * TQ * NMELS_R;
    float* out_h    = out_done + (long long)BATCH * TQ * 2;

    float *h, *big, *peq, *pek;
    float *inh, *inl, *valh, *vall, *wfh, *wfl, *fcwh, *fcwl, *cwh, *cwl;
    float *w1h, *w1l, *w2h, *w2l, *w3h, *w3l, *woh, *wol, *mwh, *mwl;
    float *hh, *hl, *h2h, *h2l, *qinh, *qinl, *kinh, *kinl;
    float *koh, *kol, *voh, *vol, *bh, *bl, *cxh, *cxl;
    SYM(h, g_h);       SYM(big, g_big);   SYM(peq, g_peq);   SYM(pek, g_pek);
    SYM(inh, g_inh);   SYM(inl, g_inl);   SYM(valh, g_valh); SYM(vall, g_vall);
    SYM(wfh, g_wfh);   SYM(wfl, g_wfl);   SYM(fcwh, g_fcwh); SYM(fcwl, g_fcwl);
    SYM(cwh, g_cwh);   SYM(cwl, g_cwl);
    SYM(w1h, g_w1h);   SYM(w1l, g_w1l);   SYM(w2h, g_w2h);   SYM(w2l, g_w2l);
    SYM(w3h, g_w3h);   SYM(w3l, g_w3l);   SYM(woh, g_woh);   SYM(wol, g_wol);
    SYM(mwh, g_mwh);   SYM(mwl, g_mwl);
    SYM(hh, g_hh);     SYM(hl, g_hl);     SYM(h2h, g_h2h);   SYM(h2l, g_h2l);
    SYM(qinh, g_qinh); SYM(qinl, g_qinl); SYM(kinh, g_kinh); SYM(kinl, g_kinl);
    SYM(koh, g_koh);   SYM(kol, g_kol);   SYM(voh, g_voh);   SYM(vol, g_vol);
    SYM(bh, g_bh);     SYM(bl, g_bl);     SYM(cxh, g_cxh);   SYM(cxl, g_cxl);

    cudaFuncSetAttribute(gemm_kernel<A_NORMAL, false, E_RELU, true,  false>, cudaFuncAttributeMaxDynamicSharedMemorySize, GSMEM_BYTES);
    cudaFuncSetAttribute(gemm_kernel<A_NORMAL, false, E_RELU, true,  true>,  cudaFuncAttributeMaxDynamicSharedMemorySize, GSMEM_BYTES);
    cudaFuncSetAttribute(gemm_kernel<A_CONV,   false, E_BIAS, false, true>,  cudaFuncAttributeMaxDynamicSharedMemorySize, GSMEM_BYTES);
    cudaFuncSetAttribute(gemm_kernel<A_NORMAL, false, E_BIAS, true,  false>, cudaFuncAttributeMaxDynamicSharedMemorySize, GSMEM_BYTES);
    cudaFuncSetAttribute(gemm_kernel<A_NORMAL, true,  E_NONE, false, true>,  cudaFuncAttributeMaxDynamicSharedMemorySize, GSMEM_BYTES);
    cudaFuncSetAttribute(gemm_kernel<A_NORMAL, false, E_SCALE,true,  false>, cudaFuncAttributeMaxDynamicSharedMemorySize, GSMEM_BYTES);
    cudaFuncSetAttribute(gemm_kernel<A_NORMAL, false, E_RESID,true,  true>,  cudaFuncAttributeMaxDynamicSharedMemorySize, GSMEM_BYTES);
    cudaFuncSetAttribute(gemm_kernel<A_NORMAL, false, E_BIAS, false, true>,  cudaFuncAttributeMaxDynamicSharedMemorySize, GSMEM_BYTES);

    const int M  = BATCH * TQ;    // 32768
    const int Mk = BATCH * TKV;   // 16384
    const float rsqrt_tk = 1.0f / sqrtf((float)TKV);

    // ---- pre-split static operands ----
    auto sp = [&](const float* s, float* ph, float* pl, int n) {
        split_kernel<<<(n + 255) / 256, 256>>>(s, ph, pl, n);
    };
    sp(inputs, inh, inl, M * NMELS_R);
    sp(values, valh, vall, Mk * EMBED);
    sp(w_first, wfh, wfl, NMELS_R * EMBED);
    sp(fc_w, fcwh, fcwl, 3 * EMBED * EMBED);
    sp(conv_w, cwh, cwl, NLAYERS * 5 * EMBED * 512);
    sp(att_w1, w1h, w1l, NLAYERS * EMBED * EMBED);
    sp(att_w2, w2h, w2l, NLAYERS * EMBED * EMBED);
    sp(att_w3, w3h, w3l, NLAYERS * EMBED * EMBED);
    sp(att_wo, woh, wol, NLAYERS * EMBED * EMBED);
    sp(w_mel, mwh, mwl, EMBED * NMELS_R);

    posenc_kernel<<<(TQ * EMBED + 255) / 256, 256>>>(peq, TQ, 1.0f);
    posenc_kernel<<<(TKV * EMBED + 255) / 256, 256>>>(pek, TKV, 2.0f);
    addpe_kernel<<<(Mk * EMBED + 255) / 256, 256>>>(keys, pek, kinh, kinl, TKV);

    // first: h2 = relu(inputs @ w_first + b) -> split only
    gemm_kernel<A_NORMAL, false, E_RELU, true, false><<<gemm_grid(M, EMBED, 1), 256, GSMEM_BYTES>>>(
        inh, inl, wfh, wfl, nullptr, h2h, h2l, b_first, nullptr,
        M, EMBED, NMELS_R, 0, 0, 0, 0, 0.0f);
    // fc0: h2 -> h(split); fc1: h -> h2(split); fc2: h2 -> h(f32 + split)
    gemm_kernel<A_NORMAL, false, E_RELU, true, false><<<gemm_grid(M, EMBED, 1), 256, GSMEM_BYTES>>>(
        h2h, h2l, fcwh, fcwl, nullptr, hh, hl, fc_b, nullptr,
        M, EMBED, EMBED, 0, 0, 0, 0, 0.0f);
    gemm_kernel<A_NORMAL, false, E_RELU, true, false><<<gemm_grid(M, EMBED, 1), 256, GSMEM_BYTES>>>(
        hh, hl, fcwh + 65536, fcwl + 65536, nullptr, h2h, h2l, fc_b + EMBED, nullptr,
        M, EMBED, EMBED, 0, 0, 0, 0, 0.0f);
    gemm_kernel<A_NORMAL, false, E_RELU, true, true><<<gemm_grid(M, EMBED, 1), 256, GSMEM_BYTES>>>(
        h2h, h2l, fcwh + 131072, fcwl + 131072, h, hh, hl, fc_b + 2 * EMBED, nullptr,
        M, EMBED, EMBED, 0, 0, 0, 0, 0.0f);

    for (int i = 0; i < NLAYERS; i++) {
        const int dil = 1 << i;
        const long long co = (long long)i * 5 * EMBED * 512;
        const long long ao = (long long)i * EMBED * EMBED;

        // conv: big(f32) = gather(h split) @ conv_w + bias
        gemm_kernel<A_CONV, false, E_BIAS, false, true><<<gemm_grid(M, 512, 1), 256, GSMEM_BYTES>>>(
            hh, hl, cwh + co, cwl + co, big, nullptr, nullptr, conv_b + i * 512, nullptr,
            M, 512, 5 * EMBED, 0, 0, 0, dil, 0.0f);
        // GLU: h(f32) updated; qin split written
        glu_kernel<<<(M * EMBED + 255) / 256, 256>>>(big, h, qinh, qinl, peq);

        // qout -> h2 split
        gemm_kernel<A_NORMAL, false, E_BIAS, true, false><<<gemm_grid(M, EMBED, 1), 256, GSMEM_BYTES>>>(
            qinh, qinl, w2h + ao, w2l + ao, nullptr, h2h, h2l, att_b2 + i * EMBED, nullptr,
            M, EMBED, EMBED, 0, 0, 0, 0, 0.0f);
        // kout -> split
        gemm_kernel<A_NORMAL, false, E_BIAS, true, false><<<gemm_grid(Mk, EMBED, 1), 256, GSMEM_BYTES>>>(
            kinh, kinl, w1h + ao, w1l + ao, nullptr, koh, kol, att_b1 + i * EMBED, nullptr,
            Mk, EMBED, EMBED, 0, 0, 0, 0, 0.0f);
        // vout -> split
        gemm_kernel<A_NORMAL, false, E_BIAS, true, false><<<gemm_grid(Mk, EMBED, 1), 256, GSMEM_BYTES>>>(
            valh, vall, w3h + ao, w3l + ao, nullptr, voh, vol, att_b3 + i * EMBED, nullptr,
            Mk, EMBED, EMBED, 0, 0, 0, 0, 0.0f);

        // scores(f32) = qout @ kout^T  (batched, TRANSB)
        gemm_kernel<A_NORMAL, true, E_NONE, false, true><<<gemm_grid(TQ, TKV, BATCH), 256, GSMEM_BYTES>>>(
            h2h, h2l, koh, kol, big, nullptr, nullptr, nullptr, nullptr,
            TQ, TKV, EMBED,
            (long long)TQ * EMBED, (long long)TKV * EMBED, (long long)TQ * TKV,
            0, 0.0f);
        // softmax -> split probs
        softmax_kernel<<<M, 128>>>(big, bh, bl);
        // ctx(split) = probs @ vout * rsqrt(TK)
        gemm_kernel<A_NORMAL, false, E_SCALE, true, false><<<gemm_grid(TQ, EMBED, BATCH), 256, GSMEM_BYTES>>>(
            bh, bl, voh, vol, nullptr, cxh, cxl, nullptr, nullptr,
            TQ, EMBED, TKV,
            (long long)TQ * TKV, (long long)TKV * EMBED, (long long)TQ * EMBED,
            0, rsqrt_tk);
        // h = (ctx @ wo + bo + h) * sqrt(0.5)  -> f32 + split
        gemm_kernel<A_NORMAL, false, E_RESID, true, true><<<gemm_grid(M, EMBED, 1), 256, GSMEM_BYTES>>>(
            cxh, cxl, woh + ao, wol + ao, h, hh, hl, att_bo + i * EMBED, h,
            M, EMBED, EMBED, 0, 0, 0, 0, 0.0f);
    }

    // mel head (f32 out)
    gemm_kernel<A_NORMAL, false, E_BIAS, false, true><<<gemm_grid(M, NMELS_R, 1), 256, GSMEM_BYTES>>>(
        hh, hl, mwh, mwl, out_mel, nullptr, nullptr, b_mel, nullptr,
        M, NMELS_R, EMBED, 0, 0, 0, 0, 0.0f);
    done_kernel<<<(M + 7) / 8, 256>>>(h, w_done, b_done, out_done);
    cudaMemcpyAsync(out_h, h, sizeof(float) * (size_t)M * EMBED,
                    cudaMemcpyDeviceToDevice);
}

// round 11
// speedup vs baseline: 1.2134x; 1.0472x over previous
#include <cuda_runtime.h>
#include <math.h>
#include <stdint.h>

#define EMBED 256
#define BATCH 32
#define TQ 1024
#define TKV 512
#define NMELS_R 320
#define NLAYERS 4
#define SQRT_HALF 0.70710678118654752440f
#define KTILE 16

// ---------------- scratch (device globals; no allocation allowed) ----------------
__device__ float g_h   [BATCH * TQ * EMBED];
__device__ float g_h2  [BATCH * TQ * EMBED];
__device__ float g_ctx [BATCH * TQ * EMBED];
__device__ float g_qin [BATCH * TQ * EMBED];
__device__ float g_kin [BATCH * TKV * EMBED];
__device__ float g_kout[BATCH * TKV * EMBED];
__device__ float g_vout[BATCH * TKV * EMBED];
__device__ float g_big [BATCH * TQ * 512];
__device__ float g_peq [TQ * EMBED];
__device__ float g_pek [TKV * EMBED];

// ---------------- cp.async helpers ----------------
__device__ __forceinline__ uint32_t smem_u32(const void* p) {
    return (uint32_t)__cvta_generic_to_shared(p);
}
__device__ __forceinline__ void cp_async16(uint32_t dst, const void* src, int src_bytes) {
    asm volatile("cp.async.cg.shared.global [%0], [%1], 16, %2;\n"
                 :: "r"(dst), "l"(src), "r"(src_bytes));
}
__device__ __forceinline__ void cp_async_commit() { asm volatile("cp.async.commit_group;\n"); }
__device__ __forceinline__ void cp_async_wait0()  { asm volatile("cp.async.wait_group 0;\n"); }

// ---------------- 3xTF32 split helpers ----------------
__device__ __forceinline__ void split_tf32(float x, uint32_t& hi, uint32_t& lo) {
    float h, l;
    asm("cvt.rna.tf32.f32 %0, %1;" : "=f"(h) : "f"(x));
    float d = x - h;
    asm("cvt.rna.tf32.f32 %0, %1;" : "=f"(l) : "f"(d));
    hi = __float_as_uint(h);
    lo = __float_as_uint(l);
}
__device__ __forceinline__ void mma_tf32(float* c, const uint32_t* a, const uint32_t* b) {
    asm volatile(
        "mma.sync.aligned.m16n8k8.row.col.f32.tf32.tf32.f32 "
        "{%0,%1,%2,%3}, {%4,%5,%6,%7}, {%8,%9}, {%0,%1,%2,%3};"
        : "+f"(c[0]), "+f"(c[1]), "+f"(c[2]), "+f"(c[3])
        : "r"(a[0]), "r"(a[1]), "r"(a[2]), "r"(a[3]), "r"(b[0]), "r"(b[1]));
}

// ---------------- positional encoding (VERIFIED R5 @5.5e-7 — DO NOT CHANGE) ----------------
__global__ void posenc_kernel(float* __restrict__ pe, int T, float rate) {
    int idx = blockIdx.x * blockDim.x + threadIdx.x;
    if (idx >= T * EMBED) return;
    int t = idx / EMBED;
    int c = idx - t * EMBED;
    double e = (double)(2.0f * (float)(c >> 1) / 256.0f);
    float power = (float)pow(10000.0, e);
    float recip = 1.0f / power;
    float p  = (float)t;
    float t1 = p * rate;
    float t2 = t1 * recip;
    float angle = p * t2;
    double a = (double)angle;
    pe[idx] = (c & 1) ? (float)cos(a) : (float)sin(a);
}

__global__ void addpe_kernel(const float* __restrict__ x, const float* __restrict__ pe,
                             float* __restrict__ y, int period) {
    long long idx = (long long)blockIdx.x * blockDim.x + threadIdx.x;
    long long r = idx >> 8;
    int c = (int)(idx & 255);
    int t = (int)(r & (period - 1));
    y[idx] = x[idx] + pe[t * EMBED + c];
}

// ---------------- TF32 tensor-core GEMM, 512 threads, cp.async double buffer ----------------
enum AMode { A_NORMAL = 0, A_CONV = 2 };
enum Epi   { E_RELU = 0, E_BIAS = 1, E_NONE = 2, E_SCALE = 3, E_RESID = 4 };

// C[M,N] = epi( A[M,K] @ B[K,N] );  TRANSB: B stored [N,K].
// 128x128x16 CTA tile, 16 warps (4x4), warp tile 32x32 via 2x4 m16n8k8, 3xTF32 split.
// A_CONV: row r -> (b=r>>10, t=r&1023); k = tap*256+ci gathers h[b, t-(4-tap)*dil, ci].
template<int AMODE, bool TRANSB, int EPI>
__global__ void __launch_bounds__(512, 1)
gemm_kernel(const float* __restrict__ A, const float* __restrict__ Bm,
            float* __restrict__ C,
            const float* __restrict__ bias,
            const float* __restrict__ resid,
            int M, int N, int K,
            long long sA, long long sB, long long sC,
            int dil, float scale)
{
    // Conflict-free padded strides (verified): A stride 20 words (20g+t distinct mod 32),
    // B stride 136 words (8t+g distinct mod 32).
    __shared__ float As[2][128][20];
    __shared__ float Bs[2][KTILE][136];

    const int bz = blockIdx.z;
    A  += bz * sA;
    Bm += bz * sB;
    C  += bz * sC;

    const int row0 = blockIdx.y * 128;
    const int col0 = blockIdx.x * 128;
    const int tid  = threadIdx.x;
    const int lane = tid & 31;
    const int warp = tid >> 5;          // 0..15
    const int m0 = (warp >> 2) * 32;    // 4 warp-rows
    const int n0 = (warp & 3) * 32;     // 4 warp-cols
    const int g = lane >> 2;
    const int t = lane & 3;

    const int nk = K / KTILE;

    // ---- tile loaders (512 threads: exactly one float4 each) ----
    auto load_A = [&](int kt, int b) {
        const int r  = tid >> 2;
        const int kc = (tid & 3) * 4;
        const int gr = row0 + r;
        const int kg = kt * KTILE + kc;
        const float* src;
        int sz = 16;
        if (AMODE == A_CONV) {
            const int tap = kg >> 8;
            const int ci  = kg & 255;
            const int shift = (4 - tap) * dil;
            const int b_ = gr >> 10;
            const int t_ = gr & 1023;
            if (t_ >= shift)
                src = A + ((size_t)((b_ << 10) + (t_ - shift))) * EMBED + ci;
            else { src = A; sz = 0; }
        } else {
            src = A + (size_t)gr * K + kg;
        }
        cp_async16(smem_u32(&As[b][r][kc]), src, sz);
    };
    auto load_B = [&](int kt, int b) {
        const int kk = tid >> 5;
        const int nc = (tid & 31) * 4;
        const int gn = col0 + nc;
        const float* src = Bm + (size_t)(kt * KTILE + kk) * N + gn;
        int sz = (gn < N) ? 16 : 0;
        if (gn >= N) src = Bm;
        cp_async16(smem_u32(&Bs[b][kk][nc]), src, sz);
    };
    float4 tb;
    auto ldg_Bt = [&](int kt) {
        const int n  = tid >> 2;
        const int kc = (tid & 3) * 4;
        const int gn = col0 + n;
        tb = (gn < N) ? *(const float4*)&Bm[(size_t)gn * K + kt * KTILE + kc]
                      : make_float4(0.f, 0.f, 0.f, 0.f);
    };
    auto sts_Bt = [&](int b) {
        const int n  = tid >> 2;
        const int kc = (tid & 3) * 4;
        Bs[b][kc + 0][n] = tb.x;
        Bs[b][kc + 1][n] = tb.y;
        Bs[b][kc + 2][n] = tb.z;
        Bs[b][kc + 3][n] = tb.w;
    };

    float acc[2][4][4];
#pragma unroll
    for (int i = 0; i < 2; i++)
#pragma unroll
        for (int j = 0; j < 4; j++)
#pragma unroll
            for (int r = 0; r < 4; r++) acc[i][j][r] = 0.0f;

    // ---- prologue ----
    load_A(0, 0);
    if (!TRANSB) {
        load_B(0, 0);
        cp_async_commit();
        cp_async_wait0();
    } else {
        cp_async_commit();
        ldg_Bt(0);
        cp_async_wait0();
        sts_Bt(0);
    }
    __syncthreads();

    for (int kt = 0; kt < nk; kt++) {
        const int cur = kt & 1;
        const int nxt = cur ^ 1;
        const bool more = (kt + 1 < nk);

        if (more) {
            load_A(kt + 1, nxt);
            if (!TRANSB) load_B(kt + 1, nxt);
            cp_async_commit();
            if (TRANSB) ldg_Bt(kt + 1);
        }

        // ---- compute on cur: 2 k8 steps ----
#pragma unroll
        for (int step = 0; step < 2; step++) {
            const int kk = step * 8;
            uint32_t ahi[2][4], alo[2][4], bhi[4][2], blo[4][2];
#pragma unroll
            for (int i = 0; i < 2; i++) {
                const int r = m0 + i * 16 + g;
                split_tf32(As[cur][r    ][kk + t    ], ahi[i][0], alo[i][0]);
                split_tf32(As[cur][r + 8][kk + t    ], ahi[i][1], alo[i][1]);
                split_tf32(As[cur][r    ][kk + t + 4], ahi[i][2], alo[i][2]);
                split_tf32(As[cur][r + 8][kk + t + 4], ahi[i][3], alo[i][3]);
            }
#pragma unroll
            for (int j = 0; j < 4; j++) {
                const int n = n0 + j * 8 + g;
                split_tf32(Bs[cur][kk + t    ][n], bhi[j][0], blo[j][0]);
                split_tf32(Bs[cur][kk + t + 4][n], bhi[j][1], blo[j][1]);
            }
#pragma unroll
            for (int i = 0; i < 2; i++)
#pragma unroll
                for (int j = 0; j < 4; j++) {
                    mma_tf32(acc[i][j], ahi[i], bhi[j]);
                    mma_tf32(acc[i][j], alo[i], bhi[j]);
                    mma_tf32(acc[i][j], ahi[i], blo[j]);
                }
        }

        if (more && TRANSB) sts_Bt(nxt);
        cp_async_wait0();
        __syncthreads();
    }

    // ---- epilogue: c0/c1 = (row, col..col+1), c2/c3 = (row+8, col..col+1) ----
#pragma unroll
    for (int i = 0; i < 2; i++) {
#pragma unroll
        for (int j = 0; j < 4; j++) {
            const int cc = col0 + n0 + j * 8 + t * 2;
            if (cc >= N) continue;
#pragma unroll
            for (int half = 0; half < 2; half++) {
                const int r = row0 + m0 + i * 16 + g + half * 8;
                float v0 = acc[i][j][half * 2 + 0];
                float v1 = acc[i][j][half * 2 + 1];
                if (EPI == E_RELU)  { v0 = fmaxf(v0 + bias[cc], 0.0f); v1 = fmaxf(v1 + bias[cc + 1], 0.0f); }
                if (EPI == E_BIAS)  { v0 += bias[cc]; v1 += bias[cc + 1]; }
                if (EPI == E_SCALE) { v0 *= scale; v1 *= scale; }
                if (EPI == E_RESID) {
                    const float2 rs = *(const float2*)&resid[(size_t)r * N + cc];
                    v0 = (v0 + bias[cc]     + rs.x) * SQRT_HALF;
                    v1 = (v1 + bias[cc + 1] + rs.y) * SQRT_HALF;
                }
                *(float2*)&C[(size_t)r * N + cc] = make_float2(v0, v1);
            }
        }
    }
}

// ---------------- GLU + residual + fused q-input ----------------
__global__ void glu_kernel(const float* __restrict__ y, float* __restrict__ h,
                           float* __restrict__ qin, const float* __restrict__ peq) {
    long long idx = (long long)blockIdx.x * blockDim.x + threadIdx.x;
    if (idx >= (long long)BATCH * TQ * EMBED) return;
    long long r = idx >> 8;
    int c = (int)(idx & 255);
    int t = (int)(r & 1023);
    float a = y[r * 512 + c];
    float g = y[r * 512 + 256 + c];
    float s = 1.0f / (1.0f + expf(-g));
    float hv = (h[idx] + a * s) * SQRT_HALF;
    h[idx] = hv;
    qin[idx] = hv + peq[t * EMBED + c];
}

// ---------------- row softmax over 512 ----------------
__global__ void softmax_kernel(float* __restrict__ x) {
    __shared__ float red[128];
    float* p = x + (long long)blockIdx.x * 512;
    const int tid = threadIdx.x;
    float v[4];
    float m = -1e30f;
#pragma unroll
    for (int i = 0; i < 4; i++) { v[i] = p[tid + i * 128]; m = fmaxf(m, v[i]); }
    red[tid] = m; __syncthreads();
#pragma unroll
    for (int s = 64; s > 0; s >>= 1) {
        if (tid < s) red[tid] = fmaxf(red[tid], red[tid + s]);
        __syncthreads();
    }
    m = red[0];
    __syncthreads();
    float sum = 0.0f;
#pragma unroll
    for (int i = 0; i < 4; i++) { v[i] = expf(v[i] - m); sum += v[i]; }
    red[tid] = sum; __syncthreads();
#pragma unroll
    for (int s = 64; s > 0; s >>= 1) {
        if (tid < s) red[tid] += red[tid + s];
        __syncthreads();
    }
    float inv = 1.0f / red[0];
#pragma unroll
    for (int i = 0; i < 4; i++) p[tid + i * 128] = v[i] * inv;
}

// ---------------- done head ----------------
__global__ void done_kernel(const float* __restrict__ h, const float* __restrict__ w,
                            const float* __restrict__ b, float* __restrict__ out) {
    const int row  = blockIdx.x * 8 + (threadIdx.x >> 5);
    const int lane = threadIdx.x & 31;
    if (row >= BATCH * TQ) return;
    const float* hr = h + (long long)row * EMBED;
    float s0 = 0.0f, s1 = 0.0f;
    for (int k = lane; k < EMBED; k += 32) {
        float hv = hr[k];
        s0 = fmaf(hv, w[k * 2 + 0], s0);
        s1 = fmaf(hv, w[k * 2 + 1], s1);
    }
#pragma unroll
    for (int o = 16; o > 0; o >>= 1) {
        s0 += __shfl_down_sync(0xffffffffu, s0, o);
        s1 += __shfl_down_sync(0xffffffffu, s1, o);
    }
    if (lane == 0) {
        out[row * 2 + 0] = 1.0f / (1.0f + expf(-(s0 + b[0])));
        out[row * 2 + 1] = 1.0f / (1.0f + expf(-(s1 + b[1])));
    }
}

// ---------------- host orchestration ----------------
static inline dim3 gemm_grid(int M, int N, int z) {
    return dim3((N + 127) / 128, (M + 127) / 128, z);
}

extern "C" void kernel_launch(void* const* d_in, const int* in_sizes, int n_in,
                              void* d_out, int out_size) {
    const float* inputs  = (const float*)d_in[0];
    const float* keys    = (const float*)d_in[1];
    const float* values  = (const float*)d_in[2];
    const float* w_first = (const float*)d_in[3];
    const float* b_first = (const float*)d_in[4];
    const float* fc_w    = (const float*)d_in[5];
    const float* fc_b    = (const float*)d_in[6];
    const float* conv_w  = (const float*)d_in[7];
    const float* conv_b  = (const float*)d_in[8];
    const float* att_w1  = (const float*)d_in[9];
    const float* att_b1  = (const float*)d_in[10];
    const float* att_w2  = (const float*)d_in[11];
    const float* att_b2  = (const float*)d_in[12];
    const float* att_w3  = (const float*)d_in[13];
    const float* att_b3  = (const float*)d_in[14];
    const float* att_wo  = (const float*)d_in[15];
    const float* att_bo  = (const float*)d_in[16];
    const float* w_done  = (const float*)d_in[17];
    const float* b_done  = (const float*)d_in[18];
    const float* w_mel   = (const float*)d_in[19];
    const float* b_mel   = (const float*)d_in[20];

    float* out      = (float*)d_out;
    float* out_mel  = out;
    float* out_done = out + (long long)BATCH * TQ * NMELS_R;
    float* out_h    = out_done + (long long)BATCH * TQ * 2;

    float *h, *h2, *ctx, *qin, *kin, *kout, *vout, *big, *peq, *pek;
    cudaGetSymbolAddress((void**)&h,    g_h);
    cudaGetSymbolAddress((void**)&h2,   g_h2);
    cudaGetSymbolAddress((void**)&ctx,  g_ctx);
    cudaGetSymbolAddress((void**)&qin,  g_qin);
    cudaGetSymbolAddress((void**)&kin,  g_kin);
    cudaGetSymbolAddress((void**)&kout, g_kout);
    cudaGetSymbolAddress((void**)&vout, g_vout);
    cudaGetSymbolAddress((void**)&big,  g_big);
    cudaGetSymbolAddress((void**)&peq,  g_peq);
    cudaGetSymbolAddress((void**)&pek,  g_pek);

    const int M  = BATCH * TQ;    // 32768
    const int Mk = BATCH * TKV;   // 16384
    const float rsqrt_tk = 1.0f / sqrtf((float)TKV);

    posenc_kernel<<<(TQ * EMBED + 255) / 256, 256>>>(peq, TQ, 1.0f);
    posenc_kernel<<<(TKV * EMBED + 255) / 256, 256>>>(pek, TKV, 2.0f);
    addpe_kernel<<<(Mk * EMBED + 255) / 256, 256>>>(keys, pek, kin, TKV);

    gemm_kernel<A_NORMAL, false, E_RELU><<<gemm_grid(M, EMBED, 1), 512>>>(
        inputs, w_first, h2, b_first, nullptr,
        M, EMBED, NMELS_R, 0, 0, 0, 0, 0.0f);
    gemm_kernel<A_NORMAL, false, E_RELU><<<gemm_grid(M, EMBED, 1), 512>>>(
        h2, fc_w + 0 * EMBED * EMBED, h, fc_b + 0 * EMBED, nullptr,
        M, EMBED, EMBED, 0, 0, 0, 0, 0.0f);
    gemm_kernel<A_NORMAL, false, E_RELU><<<gemm_grid(M, EMBED, 1), 512>>>(
        h, fc_w + 1 * EMBED * EMBED, h2, fc_b + 1 * EMBED, nullptr,
        M, EMBED, EMBED, 0, 0, 0, 0, 0.0f);
    gemm_kernel<A_NORMAL, false, E_RELU><<<gemm_grid(M, EMBED, 1), 512>>>(
        h2, fc_w + 2 * EMBED * EMBED, h, fc_b + 2 * EMBED, nullptr,
        M, EMBED, EMBED, 0, 0, 0, 0, 0.0f);

    for (int i = 0; i < NLAYERS; i++) {
        const int dil = 1 << i;
        gemm_kernel<A_CONV, false, E_BIAS><<<gemm_grid(M, 512, 1), 512>>>(
            h, conv_w + (long long)i * 5 * EMBED * 512, big,
            conv_b + i * 512, nullptr,
            M, 512, 5 * EMBED, 0, 0, 0, dil, 0.0f);
        glu_kernel<<<(M * EMBED + 255) / 256, 256>>>(big, h, qin, peq);

        gemm_kernel<A_NORMAL, false, E_BIAS><<<gemm_grid(M, EMBED, 1), 512>>>(
            qin, att_w2 + (long long)i * EMBED * EMBED, h2,
            att_b2 + i * EMBED, nullptr,
            M, EMBED, EMBED, 0, 0, 0, 0, 0.0f);
        gemm_kernel<A_NORMAL, false, E_BIAS><<<gemm_grid(Mk, EMBED, 1), 512>>>(
            kin, att_w1 + (long long)i * EMBED * EMBED, kout,
            att_b1 + i * EMBED, nullptr,
            Mk, EMBED, EMBED, 0, 0, 0, 0, 0.0f);
        gemm_kernel<A_NORMAL, false, E_BIAS><<<gemm_grid(Mk, EMBED, 1), 512>>>(
            values, att_w3 + (long long)i * EMBED * EMBED, vout,
            att_b3 + i * EMBED, nullptr,
            Mk, EMBED, EMBED, 0, 0, 0, 0, 0.0f);

        gemm_kernel<A_NORMAL, true, E_NONE><<<gemm_grid(TQ, TKV, BATCH), 512>>>(
            h2, kout, big, nullptr, nullptr,
            TQ, TKV, EMBED,
            (long long)TQ * EMBED, (long long)TKV * EMBED, (long long)TQ * TKV,
            0, 0.0f);
        softmax_kernel<<<M, 128>>>(big);
        gemm_kernel<A_NORMAL, false, E_SCALE><<<gemm_grid(TQ, EMBED, BATCH), 512>>>(
            big, vout, ctx, nullptr, nullptr,
            TQ, EMBED, TKV,
            (long long)TQ * TKV, (long long)TKV * EMBED, (long long)TQ * EMBED,
            0, rsqrt_tk);
        gemm_kernel<A_NORMAL, false, E_RESID><<<gemm_grid(M, EMBED, 1), 512>>>(
            ctx, att_wo + (long long)i * EMBED * EMBED, h,
            att_bo + i * EMBED, h,
            M, EMBED, EMBED, 0, 0, 0, 0, 0.0f);
    }

    gemm_kernel<A_NORMAL, false, E_BIAS><<<gemm_grid(M, NMELS_R, 1), 512>>>(
        h, w_mel, out_mel, b_mel, nullptr,
        M, NMELS_R, EMBED, 0, 0, 0, 0, 0.0f);
    done_kernel<<<(M + 7) / 8, 256>>>(h, w_done, b_done, out_done);
    cudaMemcpyAsync(out_h, h, sizeof(float) * (size_t)M * EMBED,
                    cudaMemcpyDeviceToDevice);
}

// round 12
// speedup vs baseline: 1.3542x; 1.1160x over previous
#include <cuda_runtime.h>
#include <math.h>
#include <stdint.h>

#define EMBED 256
#define BATCH 32
#define TQ 1024
#define TKV 512
#define NMELS_R 320
#define NLAYERS 4
#define SQRT_HALF 0.70710678118654752440f
#define KTILE 16

// ---------------- scratch (device globals; no allocation allowed) ----------------
__device__ float g_h   [BATCH * TQ * EMBED];
__device__ float g_h2  [BATCH * TQ * EMBED];
__device__ float g_ctx [BATCH * TQ * EMBED];
__device__ float g_qin [BATCH * TQ * EMBED];
__device__ float g_kin [BATCH * TKV * EMBED];
__device__ float g_kout[BATCH * TKV * EMBED];
__device__ float g_vout[BATCH * TKV * EMBED];
__device__ float g_big [BATCH * TQ * 512];
__device__ float g_peq [TQ * EMBED];
__device__ float g_pek [TKV * EMBED];

// ---------------- cp.async helpers ----------------
__device__ __forceinline__ uint32_t smem_u32(const void* p) {
    return (uint32_t)__cvta_generic_to_shared(p);
}
__device__ __forceinline__ void cp_async16(uint32_t dst, const void* src, int src_bytes) {
    asm volatile("cp.async.cg.shared.global [%0], [%1], 16, %2;\n"
                 :: "r"(dst), "l"(src), "r"(src_bytes));
}
__device__ __forceinline__ void cp_async_commit() { asm volatile("cp.async.commit_group;\n"); }
__device__ __forceinline__ void cp_async_wait0()  { asm volatile("cp.async.wait_group 0;\n"); }

// ---------------- 2-op truncation split (replaces 3-op cvt split) ----------------
// hi = x with low 13 mantissa bits masked (exactly tf32-representable; LOP3).
// lo = x - hi (exact FADD; Sterbenz). lo is fed to the MMA as raw f32 — HW reads
// the tf32 bit-subset, adding <= 2^-22 relative error (same order as 3-cvt split).
__device__ __forceinline__ void split_tf32(float x, uint32_t& hi, uint32_t& lo) {
    uint32_t h = __float_as_uint(x) & 0xFFFFE000u;
    hi = h;
    lo = __float_as_uint(x - __uint_as_float(h));
}
__device__ __forceinline__ void mma_tf32(float* c, const uint32_t* a, const uint32_t* b) {
    asm volatile(
        "mma.sync.aligned.m16n8k8.row.col.f32.tf32.tf32.f32 "
        "{%0,%1,%2,%3}, {%4,%5,%6,%7}, {%8,%9}, {%0,%1,%2,%3};"
        : "+f"(c[0]), "+f"(c[1]), "+f"(c[2]), "+f"(c[3])
        : "r"(a[0]), "r"(a[1]), "r"(a[2]), "r"(a[3]), "r"(b[0]), "r"(b[1]));
}

// ---------------- positional encoding (VERIFIED R5 @5.5e-7 — DO NOT CHANGE) ----------------
__global__ void posenc_kernel(float* __restrict__ pe, int T, float rate) {
    int idx = blockIdx.x * blockDim.x + threadIdx.x;
    if (idx >= T * EMBED) return;
    int t = idx / EMBED;
    int c = idx - t * EMBED;
    double e = (double)(2.0f * (float)(c >> 1) / 256.0f);
    float power = (float)pow(10000.0, e);
    float recip = 1.0f / power;
    float p  = (float)t;
    float t1 = p * rate;
    float t2 = t1 * recip;
    float angle = p * t2;
    double a = (double)angle;
    pe[idx] = (c & 1) ? (float)cos(a) : (float)sin(a);
}

__global__ void addpe_kernel(const float* __restrict__ x, const float* __restrict__ pe,
                             float* __restrict__ y, int period) {
    long long idx = (long long)blockIdx.x * blockDim.x + threadIdx.x;
    long long r = idx >> 8;
    int c = (int)(idx & 255);
    int t = (int)(r & (period - 1));
    y[idx] = x[idx] + pe[t * EMBED + c];
}

// ---------------- TF32 tensor-core GEMM, double-buffered cp.async ----------------
enum AMode { A_NORMAL = 0, A_CONV = 2 };
enum Epi   { E_RELU = 0, E_BIAS = 1, E_NONE = 2, E_SCALE = 3, E_RESID = 4 };

// C[M,N] = epi( A[M,K] @ B[K,N] );  TRANSB: B stored [N,K].
// 128x128x16 CTA tile, 8 warps (2x4), warp tile 64x32 via 4x4 m16n8k8 mma.
// A_CONV: row r -> (b=r>>10, t=r&1023); k = tap*256+ci gathers h[b, t-(4-tap)*dil, ci].
template<int AMODE, bool TRANSB, int EPI>
__global__ void __launch_bounds__(256, 1)
gemm_kernel(const float* __restrict__ A, const float* __restrict__ Bm,
            float* __restrict__ C,
            const float* __restrict__ bias,
            const float* __restrict__ resid,
            int M, int N, int K,
            long long sA, long long sB, long long sC,
            int dil, float scale)
{
    // Padded strides chosen for conflict-free mma-fragment LDS:
    // A row stride 20 words; B row stride 136 words (hand-verified distinct banks).
    __shared__ float As[2][128][20];
    __shared__ float Bs[2][KTILE][136];

    const int bz = blockIdx.z;
    A  += bz * sA;
    Bm += bz * sB;
    C  += bz * sC;

    const int row0 = blockIdx.y * 128;
    const int col0 = blockIdx.x * 128;
    const int tid  = threadIdx.x;
    const int lane = tid & 31;
    const int warp = tid >> 5;
    const int wm = warp >> 2;          // 0..1
    const int wn = warp & 3;           // 0..3
    const int m0 = wm * 64;
    const int n0 = wn * 32;
    const int g = lane >> 2;           // 0..7
    const int t = lane & 3;            // 0..3

    const int nk = K / KTILE;

    // ---- tile loaders ----
    auto load_A = [&](int kt, int b) {
#pragma unroll
        for (int u = 0; u < 2; u++) {
            const int idx = tid + u * 256;
            const int r  = idx >> 2;
            const int kc = (idx & 3) * 4;
            const int gr = row0 + r;
            const int kg = kt * KTILE + kc;
            const float* src;
            int sz = 16;
            if (AMODE == A_CONV) {
                const int tap = kg >> 8;
                const int ci  = kg & 255;
                const int shift = (4 - tap) * dil;
                const int b_ = gr >> 10;
                const int t_ = gr & 1023;
                if (t_ >= shift)
                    src = A + ((long long)((b_ << 10) + (t_ - shift))) * EMBED + ci;
                else { src = A; sz = 0; }
            } else {
                src = A + (long long)gr * K + kg;
            }
            cp_async16(smem_u32(&As[b][r][kc]), src, sz);
        }
    };
    auto load_B = [&](int kt, int b) {
#pragma unroll
        for (int u = 0; u < 2; u++) {
            const int idx = tid + u * 256;
            const int kk = idx >> 5;
            const int nc = (idx & 31) * 4;
            const int gn = col0 + nc;
            const float* src = Bm + (long long)(kt * KTILE + kk) * N + gn;
            int sz = (gn < N) ? 16 : 0;
            if (gn >= N) src = Bm;
            cp_async16(smem_u32(&Bs[b][kk][nc]), src, sz);
        }
    };
    float4 tb[2];
    auto ldg_Bt = [&](int kt) {
#pragma unroll
        for (int u = 0; u < 2; u++) {
            const int idx = tid + u * 256;
            const int n  = idx >> 2;
            const int kc = (idx & 3) * 4;
            const int gn = col0 + n;
            tb[u] = (gn < N) ? *(const float4*)&Bm[(long long)gn * K + kt * KTILE + kc]
                             : make_float4(0.f, 0.f, 0.f, 0.f);
        }
    };
    auto sts_Bt = [&](int b) {
#pragma unroll
        for (int u = 0; u < 2; u++) {
            const int idx = tid + u * 256;
            const int n  = idx >> 2;
            const int kc = (idx & 3) * 4;
            Bs[b][kc + 0][n] = tb[u].x;
            Bs[b][kc + 1][n] = tb[u].y;
            Bs[b][kc + 2][n] = tb[u].z;
            Bs[b][kc + 3][n] = tb[u].w;
        }
    };

    float acc[4][4][4];
#pragma unroll
    for (int i = 0; i < 4; i++)
#pragma unroll
        for (int j = 0; j < 4; j++)
#pragma unroll
            for (int r = 0; r < 4; r++) acc[i][j][r] = 0.0f;

    // ---- prologue ----
    load_A(0, 0);
    if (!TRANSB) {
        load_B(0, 0);
        cp_async_commit();
        cp_async_wait0();
    } else {
        cp_async_commit();
        ldg_Bt(0);
        cp_async_wait0();
        sts_Bt(0);
    }
    __syncthreads();

    for (int kt = 0; kt < nk; kt++) {
        const int cur = kt & 1;
        const int nxt = cur ^ 1;
        const bool more = (kt + 1 < nk);

        if (more) {
            load_A(kt + 1, nxt);
            if (!TRANSB) load_B(kt + 1, nxt);
            cp_async_commit();
            if (TRANSB) ldg_Bt(kt + 1);
        }

        // ---- compute on cur: 2 k8 steps ----
#pragma unroll
        for (int step = 0; step < 2; step++) {
            const int kk = step * 8;
            uint32_t ahi[4][4], alo[4][4], bhi[4][2], blo[4][2];
#pragma unroll
            for (int i = 0; i < 4; i++) {
                const int r = m0 + i * 16 + g;
                split_tf32(As[cur][r    ][kk + t    ], ahi[i][0], alo[i][0]);
                split_tf32(As[cur][r + 8][kk + t    ], ahi[i][1], alo[i][1]);
                split_tf32(As[cur][r    ][kk + t + 4], ahi[i][2], alo[i][2]);
                split_tf32(As[cur][r + 8][kk + t + 4], ahi[i][3], alo[i][3]);
            }
#pragma unroll
            for (int j = 0; j < 4; j++) {
                const int n = n0 + j * 8 + g;
                split_tf32(Bs[cur][kk + t    ][n], bhi[j][0], blo[j][0]);
                split_tf32(Bs[cur][kk + t + 4][n], bhi[j][1], blo[j][1]);
            }
#pragma unroll
            for (int i = 0; i < 4; i++)
#pragma unroll
                for (int j = 0; j < 4; j++) {
                    mma_tf32(acc[i][j], ahi[i], bhi[j]);
                    mma_tf32(acc[i][j], alo[i], bhi[j]);
                    mma_tf32(acc[i][j], ahi[i], blo[j]);
                }
        }

        if (more && TRANSB) sts_Bt(nxt);
        cp_async_wait0();
        __syncthreads();
    }

    // ---- epilogue: c0/c1 = (row, col..col+1), c2/c3 = (row+8, col..col+1) ----
#pragma unroll
    for (int i = 0; i < 4; i++) {
#pragma unroll
        for (int j = 0; j < 4; j++) {
            const int cc = col0 + n0 + j * 8 + t * 2;
            if (cc >= N) continue;
#pragma unroll
            for (int half = 0; half < 2; half++) {
                const int r = row0 + m0 + i * 16 + g + half * 8;
                float v0 = acc[i][j][half * 2 + 0];
                float v1 = acc[i][j][half * 2 + 1];
                if (EPI == E_RELU)  { v0 = fmaxf(v0 + bias[cc], 0.0f); v1 = fmaxf(v1 + bias[cc + 1], 0.0f); }
                if (EPI == E_BIAS)  { v0 += bias[cc]; v1 += bias[cc + 1]; }
                if (EPI == E_SCALE) { v0 *= scale; v1 *= scale; }
                if (EPI == E_RESID) {
                    const float2 rs = *(const float2*)&resid[(long long)r * N + cc];
                    v0 = (v0 + bias[cc]     + rs.x) * SQRT_HALF;
                    v1 = (v1 + bias[cc + 1] + rs.y) * SQRT_HALF;
                }
                *(float2*)&C[(long long)r * N + cc] = make_float2(v0, v1);
            }
        }
    }
}

// ---------------- GLU + residual + fused q-input ----------------
__global__ void glu_kernel(const float* __restrict__ y, float* __restrict__ h,
                           float* __restrict__ qin, const float* __restrict__ peq) {
    long long idx = (long long)blockIdx.x * blockDim.x + threadIdx.x;
    if (idx >= (long long)BATCH * TQ * EMBED) return;
    long long r = idx >> 8;
    int c = (int)(idx & 255);
    int t = (int)(r & 1023);
    float a = y[r * 512 + c];
    float g = y[r * 512 + 256 + c];
    float s = 1.0f / (1.0f + expf(-g));
    float hv = (h[idx] + a * s) * SQRT_HALF;
    h[idx] = hv;
    qin[idx] = hv + peq[t * EMBED + c];
}

// ---------------- row softmax over 512 ----------------
__global__ void softmax_kernel(float* __restrict__ x) {
    __shared__ float red[128];
    float* p = x + (long long)blockIdx.x * 512;
    const int tid = threadIdx.x;
    float v[4];
    float m = -1e30f;
#pragma unroll
    for (int i = 0; i < 4; i++) { v[i] = p[tid + i * 128]; m = fmaxf(m, v[i]); }
    red[tid] = m; __syncthreads();
#pragma unroll
    for (int s = 64; s > 0; s >>= 1) {
        if (tid < s) red[tid] = fmaxf(red[tid], red[tid + s]);
        __syncthreads();
    }
    m = red[0];
    __syncthreads();
    float sum = 0.0f;
#pragma unroll
    for (int i = 0; i < 4; i++) { v[i] = expf(v[i] - m); sum += v[i]; }
    red[tid] = sum; __syncthreads();
#pragma unroll
    for (int s = 64; s > 0; s >>= 1) {
        if (tid < s) red[tid] += red[tid + s];
        __syncthreads();
    }
    float inv = 1.0f / red[0];
#pragma unroll
    for (int i = 0; i < 4; i++) p[tid + i * 128] = v[i] * inv;
}

// ---------------- done head ----------------
__global__ void done_kernel(const float* __restrict__ h, const float* __restrict__ w,
                            const float* __restrict__ b, float* __restrict__ out) {
    const int row  = blockIdx.x * 8 + (threadIdx.x >> 5);
    const int lane = threadIdx.x & 31;
    if (row >= BATCH * TQ) return;
    const float* hr = h + (long long)row * EMBED;
    float s0 = 0.0f, s1 = 0.0f;
    for (int k = lane; k < EMBED; k += 32) {
        float hv = hr[k];
        s0 = fmaf(hv, w[k * 2 + 0], s0);
        s1 = fmaf(hv, w[k * 2 + 1], s1);
    }
#pragma unroll
    for (int o = 16; o > 0; o >>= 1) {
        s0 += __shfl_down_sync(0xffffffffu, s0, o);
        s1 += __shfl_down_sync(0xffffffffu, s1, o);
    }
    if (lane == 0) {
        out[row * 2 + 0] = 1.0f / (1.0f + expf(-(s0 + b[0])));
        out[row * 2 + 1] = 1.0f / (1.0f + expf(-(s1 + b[1])));
    }
}

// ---------------- host orchestration ----------------
static inline dim3 gemm_grid(int M, int N, int z) {
    return dim3((N + 127) / 128, (M + 127) / 128, z);
}

extern "C" void kernel_launch(void* const* d_in, const int* in_sizes, int n_in,
                              void* d_out, int out_size) {
    const float* inputs  = (const float*)d_in[0];
    const float* keys    = (const float*)d_in[1];
    const float* values  = (const float*)d_in[2];
    const float* w_first = (const float*)d_in[3];
    const float* b_first = (const float*)d_in[4];
    const float* fc_w    = (const float*)d_in[5];
    const float* fc_b    = (const float*)d_in[6];
    const float* conv_w  = (const float*)d_in[7];
    const float* conv_b  = (const float*)d_in[8];
    const float* att_w1  = (const float*)d_in[9];
    const float* att_b1  = (const float*)d_in[10];
    const float* att_w2  = (const float*)d_in[11];
    const float* att_b2  = (const float*)d_in[12];
    const float* att_w3  = (const float*)d_in[13];
    const float* att_b3  = (const float*)d_in[14];
    const float* att_wo  = (const float*)d_in[15];
    const float* att_bo  = (const float*)d_in[16];
    const float* w_done  = (const float*)d_in[17];
    const float* b_done  = (const float*)d_in[18];
    const float* w_mel   = (const float*)d_in[19];
    const float* b_mel   = (const float*)d_in[20];

    float* out      = (float*)d_out;
    float* out_mel  = out;
    float* out_done = out + (long long)BATCH * TQ * NMELS_R;
    float* out_h    = out_done + (long long)BATCH * TQ * 2;

    float *h, *h2, *ctx, *qin, *kin, *kout, *vout, *big, *peq, *pek;
    cudaGetSymbolAddress((void**)&h,    g_h);
    cudaGetSymbolAddress((void**)&h2,   g_h2);
    cudaGetSymbolAddress((void**)&ctx,  g_ctx);
    cudaGetSymbolAddress((void**)&qin,  g_qin);
    cudaGetSymbolAddress((void**)&kin,  g_kin);
    cudaGetSymbolAddress((void**)&kout, g_kout);
    cudaGetSymbolAddress((void**)&vout, g_vout);
    cudaGetSymbolAddress((void**)&big,  g_big);
    cudaGetSymbolAddress((void**)&peq,  g_peq);
    cudaGetSymbolAddress((void**)&pek,  g_pek);

    const int M  = BATCH * TQ;    // 32768
    const int Mk = BATCH * TKV;   // 16384
    const float rsqrt_tk = 1.0f / sqrtf((float)TKV);

    posenc_kernel<<<(TQ * EMBED + 255) / 256, 256>>>(peq, TQ, 1.0f);
    posenc_kernel<<<(TKV * EMBED + 255) / 256, 256>>>(pek, TKV, 2.0f);
    addpe_kernel<<<(Mk * EMBED + 255) / 256, 256>>>(keys, pek, kin, TKV);

    gemm_kernel<A_NORMAL, false, E_RELU><<<gemm_grid(M, EMBED, 1), 256>>>(
        inputs, w_first, h2, b_first, nullptr,
        M, EMBED, NMELS_R, 0, 0, 0, 0, 0.0f);
    gemm_kernel<A_NORMAL, false, E_RELU><<<gemm_grid(M, EMBED, 1), 256>>>(
        h2, fc_w + 0 * EMBED * EMBED, h, fc_b + 0 * EMBED, nullptr,
        M, EMBED, EMBED, 0, 0, 0, 0, 0.0f);
    gemm_kernel<A_NORMAL, false, E_RELU><<<gemm_grid(M, EMBED, 1), 256>>>(
        h, fc_w + 1 * EMBED * EMBED, h2, fc_b + 1 * EMBED, nullptr,
        M, EMBED, EMBED, 0, 0, 0, 0, 0.0f);
    gemm_kernel<A_NORMAL, false, E_RELU><<<gemm_grid(M, EMBED, 1), 256>>>(
        h2, fc_w + 2 * EMBED * EMBED, h, fc_b + 2 * EMBED, nullptr,
        M, EMBED, EMBED, 0, 0, 0, 0, 0.0f);

    for (int i = 0; i < NLAYERS; i++) {
        const int dil = 1 << i;
        gemm_kernel<A_CONV, false, E_BIAS><<<gemm_grid(M, 512, 1), 256>>>(
            h, conv_w + (long long)i * 5 * EMBED * 512, big,
            conv_b + i * 512, nullptr,
            M, 512, 5 * EMBED, 0, 0, 0, dil, 0.0f);
        glu_kernel<<<(M * EMBED + 255) / 256, 256>>>(big, h, qin, peq);

        gemm_kernel<A_NORMAL, false, E_BIAS><<<gemm_grid(M, EMBED, 1), 256>>>(
            qin, att_w2 + (long long)i * EMBED * EMBED, h2,
            att_b2 + i * EMBED, nullptr,
            M, EMBED, EMBED, 0, 0, 0, 0, 0.0f);
        gemm_kernel<A_NORMAL, false, E_BIAS><<<gemm_grid(Mk, EMBED, 1), 256>>>(
            kin, att_w1 + (long long)i * EMBED * EMBED, kout,
            att_b1 + i * EMBED, nullptr,
            Mk, EMBED, EMBED, 0, 0, 0, 0, 0.0f);
        gemm_kernel<A_NORMAL, false, E_BIAS><<<gemm_grid(Mk, EMBED, 1), 256>>>(
            values, att_w3 + (long long)i * EMBED * EMBED, vout,
            att_b3 + i * EMBED, nullptr,
            Mk, EMBED, EMBED, 0, 0, 0, 0, 0.0f);

        gemm_kernel<A_NORMAL, true, E_NONE><<<gemm_grid(TQ, TKV, BATCH), 256>>>(
            h2, kout, big, nullptr, nullptr,
            TQ, TKV, EMBED,
            (long long)TQ * EMBED, (long long)TKV * EMBED, (long long)TQ * TKV,
            0, 0.0f);
        softmax_kernel<<<M, 128>>>(big);
        gemm_kernel<A_NORMAL, false, E_SCALE><<<gemm_grid(TQ, EMBED, BATCH), 256>>>(
            big, vout, ctx, nullptr, nullptr,
            TQ, EMBED, TKV,
            (long long)TQ * TKV, (long long)TKV * EMBED, (long long)TQ * EMBED,
            0, rsqrt_tk);
        gemm_kernel<A_NORMAL, false, E_RESID><<<gemm_grid(M, EMBED, 1), 256>>>(
            ctx, att_wo + (long long)i * EMBED * EMBED, h,
            att_bo + i * EMBED, h,
            M, EMBED, EMBED, 0, 0, 0, 0, 0.0f);
    }

    gemm_kernel<A_NORMAL, false, E_BIAS><<<gemm_grid(M, NMELS_R, 1), 256>>>(
        h, w_mel, out_mel, b_mel, nullptr,
        M, NMELS_R, EMBED, 0, 0, 0, 0, 0.0f);
    done_kernel<<<(M + 7) / 8, 256>>>(h, w_done, b_done, out_done);
    cudaMemcpyAsync(out_h, h, sizeof(float) * (size_t)M * EMBED,
                    cudaMemcpyDeviceToDevice);
}

// round 13
// speedup vs baseline: 1.4014x; 1.0349x over previous
#include <cuda_runtime.h>
#include <math.h>
#include <stdint.h>

#define EMBED 256
#define BATCH 32
#define TQ 1024
#define TKV 512
#define NMELS_R 320
#define NLAYERS 4
#define SQRT_HALF 0.70710678118654752440f
#define KTILE 16

// smem word layout: As[2][128][20] (5120 w), Bs[2][16][264] (8448 w) => 54272 bytes
#define AS_BUF 2560
#define BS_BASE 5120
#define BS_BUF 4224
#define GSMEM_BYTES 54272

// ---------------- scratch (device globals; no allocation allowed) ----------------
__device__ float g_h   [BATCH * TQ * EMBED];
__device__ float g_h2  [BATCH * TQ * EMBED];
__device__ float g_ctx [BATCH * TQ * EMBED];
__device__ float g_qin [BATCH * TQ * EMBED];
__device__ float g_kin [BATCH * TKV * EMBED];
__device__ float g_kout[BATCH * TKV * EMBED];
__device__ float g_vout[BATCH * TKV * EMBED];
__device__ float g_big [BATCH * TQ * 512];
__device__ float g_peq [TQ * EMBED];
__device__ float g_pek [TKV * EMBED];

// ---------------- cp.async helpers ----------------
__device__ __forceinline__ uint32_t smem_u32(const void* p) {
    return (uint32_t)__cvta_generic_to_shared(p);
}
__device__ __forceinline__ void cp_async16(uint32_t dst, const void* src, int src_bytes) {
    asm volatile("cp.async.cg.shared.global [%0], [%1], 16, %2;\n"
                 :: "r"(dst), "l"(src), "r"(src_bytes));
}
__device__ __forceinline__ void cp_async_commit() { asm volatile("cp.async.commit_group;\n"); }
__device__ __forceinline__ void cp_async_wait0()  { asm volatile("cp.async.wait_group 0;\n"); }

// ---------------- 2-op truncation split (verified R12 @2.1e-5) ----------------
__device__ __forceinline__ void split_tf32(float x, uint32_t& hi, uint32_t& lo) {
    uint32_t h = __float_as_uint(x) & 0xFFFFE000u;
    hi = h;
    lo = __float_as_uint(x - __uint_as_float(h));
}
__device__ __forceinline__ void mma_tf32(float* c, const uint32_t* a, const uint32_t* b) {
    asm volatile(
        "mma.sync.aligned.m16n8k8.row.col.f32.tf32.tf32.f32 "
        "{%0,%1,%2,%3}, {%4,%5,%6,%7}, {%8,%9}, {%0,%1,%2,%3};"
        : "+f"(c[0]), "+f"(c[1]), "+f"(c[2]), "+f"(c[3])
        : "r"(a[0]), "r"(a[1]), "r"(a[2]), "r"(a[3]), "r"(b[0]), "r"(b[1]));
}

// ---------------- positional encoding (VERIFIED R5 @5.5e-7 — DO NOT CHANGE) ----------------
__global__ void posenc_kernel(float* __restrict__ pe, int T, float rate) {
    int idx = blockIdx.x * blockDim.x + threadIdx.x;
    if (idx >= T * EMBED) return;
    int t = idx / EMBED;
    int c = idx - t * EMBED;
    double e = (double)(2.0f * (float)(c >> 1) / 256.0f);
    float power = (float)pow(10000.0, e);
    float recip = 1.0f / power;
    float p  = (float)t;
    float t1 = p * rate;
    float t2 = t1 * recip;
    float angle = p * t2;
    double a = (double)angle;
    pe[idx] = (c & 1) ? (float)cos(a) : (float)sin(a);
}

__global__ void addpe_kernel(const float* __restrict__ x, const float* __restrict__ pe,
                             float* __restrict__ y, int period) {
    long long idx = (long long)blockIdx.x * blockDim.x + threadIdx.x;
    long long r = idx >> 8;
    int c = (int)(idx & 255);
    int t = (int)(r & (period - 1));
    y[idx] = x[idx] + pe[t * EMBED + c];
}

// ---------------- TF32 tensor-core GEMM, 128x256 CTA tile, 64x64 warp tiles ----------------
enum AMode { A_NORMAL = 0, A_CONV = 2 };
enum Epi   { E_RELU = 0, E_BIAS = 1, E_NONE = 2, E_SCALE = 3, E_RESID = 4 };

// C[M,N] = epi( A[M,K] @ B[K,N] );  TRANSB: B stored [N,K].
// CTA 128x256x16, 8 warps (2x4), warp tile 64x64 via 4x8 m16n8k8, 3xTF32 split.
// Cuts smem fragment redundancy: A 4x, B 2x, per 2x FLOPs (44KB/k-tile-FLOP vs 64KB).
template<int AMODE, bool TRANSB, int EPI>
__global__ void __launch_bounds__(256, 1)
gemm_kernel(const float* __restrict__ A, const float* __restrict__ Bm,
            float* __restrict__ C,
            const float* __restrict__ bias,
            const float* __restrict__ resid,
            int M, int N, int K,
            long long sA, long long sB, long long sC,
            int dil, float scale)
{
    extern __shared__ float sm[];
    const uint32_t sbase = smem_u32(sm);

    const int bz = blockIdx.z;
    A  += bz * sA;
    Bm += bz * sB;
    C  += bz * sC;

    const int row0 = blockIdx.y * 128;
    const int col0 = blockIdx.x * 256;
    const int tid  = threadIdx.x;
    const int lane = tid & 31;
    const int warp = tid >> 5;
    const int m0 = (warp >> 2) * 64;   // 2 row-bands
    const int n0 = (warp & 3) * 64;    // 4 col-bands
    const int g = lane >> 2;
    const int t = lane & 3;

    const int nk = K / KTILE;

    // ---- tile loaders ----
    // A: 128 rows x 16 k = 512 float4; 256 threads x 2
    auto load_A = [&](int kt, int b) {
#pragma unroll
        for (int u = 0; u < 2; u++) {
            const int idx = tid + u * 256;
            const int r  = idx >> 2;
            const int kc = (idx & 3) * 4;
            const int gr = row0 + r;
            const int kg = kt * KTILE + kc;
            const float* src;
            int sz = 16;
            if (AMODE == A_CONV) {
                const int tap = kg >> 8;
                const int ci  = kg & 255;
                const int shift = (4 - tap) * dil;
                const int b_ = gr >> 10;
                const int t_ = gr & 1023;
                if (t_ >= shift)
                    src = A + ((long long)((b_ << 10) + (t_ - shift))) * EMBED + ci;
                else { src = A; sz = 0; }
            } else {
                src = A + (long long)gr * K + kg;
            }
            cp_async16(smem_u32(sm) + (uint32_t)((b * AS_BUF + r * 20 + kc) * 4), src, sz);
        }
    };
    // B (non-trans): 16 k x 256 n = 1024 float4; 256 threads x 4
    auto load_B = [&](int kt, int b) {
#pragma unroll
        for (int u = 0; u < 4; u++) {
            const int idx = tid + u * 256;
            const int kk = idx >> 6;
            const int nc = (idx & 63) * 4;
            const int gn = col0 + nc;
            const float* src = Bm + (long long)(kt * KTILE + kk) * N + gn;
            int sz = (gn < N) ? 16 : 0;
            if (gn >= N) src = Bm;
            cp_async16(smem_u32(sm) + (uint32_t)((BS_BASE + b * BS_BUF + kk * 264 + nc) * 4), src, sz);
        }
    };
    // TRANSB: B stored [N,K]; 256 n-rows x 4 float4 = 1024 float4
    float4 tb[4];
    auto ldg_Bt = [&](int kt) {
#pragma unroll
        for (int u = 0; u < 4; u++) {
            const int idx = tid + u * 256;
            const int n  = idx >> 2;
            const int kc = (idx & 3) * 4;
            const int gn = col0 + n;
            tb[u] = (gn < N) ? *(const float4*)&Bm[(long long)gn * K + kt * KTILE + kc]
                             : make_float4(0.f, 0.f, 0.f, 0.f);
        }
    };
    auto sts_Bt = [&](int b) {
#pragma unroll
        for (int u = 0; u < 4; u++) {
            const int idx = tid + u * 256;
            const int n  = idx >> 2;
            const int kc = (idx & 3) * 4;
            float* base = sm + BS_BASE + b * BS_BUF;
            base[(kc + 0) * 264 + n] = tb[u].x;
            base[(kc + 1) * 264 + n] = tb[u].y;
            base[(kc + 2) * 264 + n] = tb[u].z;
            base[(kc + 3) * 264 + n] = tb[u].w;
        }
    };

    float acc[4][8][4];
#pragma unroll
    for (int i = 0; i < 4; i++)
#pragma unroll
        for (int j = 0; j < 8; j++)
#pragma unroll
            for (int r = 0; r < 4; r++) acc[i][j][r] = 0.0f;

    // ---- prologue ----
    load_A(0, 0);
    if (!TRANSB) {
        load_B(0, 0);
        cp_async_commit();
        cp_async_wait0();
    } else {
        cp_async_commit();
        ldg_Bt(0);
        cp_async_wait0();
        sts_Bt(0);
    }
    __syncthreads();

    for (int kt = 0; kt < nk; kt++) {
        const int cur = kt & 1;
        const int nxt = cur ^ 1;
        const bool more = (kt + 1 < nk);

        if (more) {
            load_A(kt + 1, nxt);
            if (!TRANSB) load_B(kt + 1, nxt);
            cp_async_commit();
            if (TRANSB) ldg_Bt(kt + 1);
        }

        const float* AsC = sm + cur * AS_BUF;
        const float* BsC = sm + BS_BASE + cur * BS_BUF;

        // ---- compute on cur: 2 k8 steps ----
#pragma unroll
        for (int step = 0; step < 2; step++) {
            const int kk = step * 8;
            uint32_t ahi[4][4], alo[4][4];
#pragma unroll
            for (int i = 0; i < 4; i++) {
                const int r = m0 + i * 16 + g;
                split_tf32(AsC[r * 20 + kk + t],           ahi[i][0], alo[i][0]);
                split_tf32(AsC[(r + 8) * 20 + kk + t],     ahi[i][1], alo[i][1]);
                split_tf32(AsC[r * 20 + kk + t + 4],       ahi[i][2], alo[i][2]);
                split_tf32(AsC[(r + 8) * 20 + kk + t + 4], ahi[i][3], alo[i][3]);
            }
#pragma unroll
            for (int j = 0; j < 8; j++) {
                const int n = n0 + j * 8 + g;
                uint32_t bh[2], bl[2];
                split_tf32(BsC[(kk + t) * 264 + n],     bh[0], bl[0]);
                split_tf32(BsC[(kk + t + 4) * 264 + n], bh[1], bl[1]);
#pragma unroll
                for (int i = 0; i < 4; i++) {
                    mma_tf32(acc[i][j], ahi[i], bh);
                    mma_tf32(acc[i][j], alo[i], bh);
                    mma_tf32(acc[i][j], ahi[i], bl);
                }
            }
        }

        if (more && TRANSB) sts_Bt(nxt);
        cp_async_wait0();
        __syncthreads();
    }

    // ---- epilogue ----
#pragma unroll
    for (int i = 0; i < 4; i++) {
#pragma unroll
        for (int j = 0; j < 8; j++) {
            const int cc = col0 + n0 + j * 8 + t * 2;
            if (cc >= N) continue;
#pragma unroll
            for (int half = 0; half < 2; half++) {
                const int r = row0 + m0 + i * 16 + g + half * 8;
                float v0 = acc[i][j][half * 2 + 0];
                float v1 = acc[i][j][half * 2 + 1];
                if (EPI == E_RELU)  { v0 = fmaxf(v0 + bias[cc], 0.0f); v1 = fmaxf(v1 + bias[cc + 1], 0.0f); }
                if (EPI == E_BIAS)  { v0 += bias[cc]; v1 += bias[cc + 1]; }
                if (EPI == E_SCALE) { v0 *= scale; v1 *= scale; }
                if (EPI == E_RESID) {
                    const float2 rs = *(const float2*)&resid[(long long)r * N + cc];
                    v0 = (v0 + bias[cc]     + rs.x) * SQRT_HALF;
                    v1 = (v1 + bias[cc + 1] + rs.y) * SQRT_HALF;
                }
                *(float2*)&C[(long long)r * N + cc] = make_float2(v0, v1);
            }
        }
    }
}

// ---------------- GLU + residual + fused q-input ----------------
__global__ void glu_kernel(const float* __restrict__ y, float* __restrict__ h,
                           float* __restrict__ qin, const float* __restrict__ peq) {
    long long idx = (long long)blockIdx.x * blockDim.x + threadIdx.x;
    if (idx >= (long long)BATCH * TQ * EMBED) return;
    long long r = idx >> 8;
    int c = (int)(idx & 255);
    int t = (int)(r & 1023);
    float a = y[r * 512 + c];
    float g = y[r * 512 + 256 + c];
    float s = 1.0f / (1.0f + expf(-g));
    float hv = (h[idx] + a * s) * SQRT_HALF;
    h[idx] = hv;
    qin[idx] = hv + peq[t * EMBED + c];
}

// ---------------- row softmax over 512 ----------------
__global__ void softmax_kernel(float* __restrict__ x) {
    __shared__ float red[128];
    float* p = x + (long long)blockIdx.x * 512;
    const int tid = threadIdx.x;
    float v[4];
    float m = -1e30f;
#pragma unroll
    for (int i = 0; i < 4; i++) { v[i] = p[tid + i * 128]; m = fmaxf(m, v[i]); }
    red[tid] = m; __syncthreads();
#pragma unroll
    for (int s = 64; s > 0; s >>= 1) {
        if (tid < s) red[tid] = fmaxf(red[tid], red[tid + s]);
        __syncthreads();
    }
    m = red[0];
    __syncthreads();
    float sum = 0.0f;
#pragma unroll
    for (int i = 0; i < 4; i++) { v[i] = expf(v[i] - m); sum += v[i]; }
    red[tid] = sum; __syncthreads();
#pragma unroll
    for (int s = 64; s > 0; s >>= 1) {
        if (tid < s) red[tid] += red[tid + s];
        __syncthreads();
    }
    float inv = 1.0f / red[0];
#pragma unroll
    for (int i = 0; i < 4; i++) p[tid + i * 128] = v[i] * inv;
}

// ---------------- done head ----------------
__global__ void done_kernel(const float* __restrict__ h, const float* __restrict__ w,
                            const float* __restrict__ b, float* __restrict__ out) {
    const int row  = blockIdx.x * 8 + (threadIdx.x >> 5);
    const int lane = threadIdx.x & 31;
    if (row >= BATCH * TQ) return;
    const float* hr = h + (long long)row * EMBED;
    float s0 = 0.0f, s1 = 0.0f;
    for (int k = lane; k < EMBED; k += 32) {
        float hv = hr[k];
        s0 = fmaf(hv, w[k * 2 + 0], s0);
        s1 = fmaf(hv, w[k * 2 + 1], s1);
    }
#pragma unroll
    for (int o = 16; o > 0; o >>= 1) {
        s0 += __shfl_down_sync(0xffffffffu, s0, o);
        s1 += __shfl_down_sync(0xffffffffu, s1, o);
    }
    if (lane == 0) {
        out[row * 2 + 0] = 1.0f / (1.0f + expf(-(s0 + b[0])));
        out[row * 2 + 1] = 1.0f / (1.0f + expf(-(s1 + b[1])));
    }
}

// ---------------- host orchestration ----------------
static inline dim3 gemm_grid(int M, int N, int z) {
    return dim3((N + 255) / 256, M / 128, z);
}

extern "C" void kernel_launch(void* const* d_in, const int* in_sizes, int n_in,
                              void* d_out, int out_size) {
    const float* inputs  = (const float*)d_in[0];
    const float* keys    = (const float*)d_in[1];
    const float* values  = (const float*)d_in[2];
    const float* w_first = (const float*)d_in[3];
    const float* b_first = (const float*)d_in[4];
    const float* fc_w    = (const float*)d_in[5];
    const float* fc_b    = (const float*)d_in[6];
    const float* conv_w  = (const float*)d_in[7];
    const float* conv_b  = (const float*)d_in[8];
    const float* att_w1  = (const float*)d_in[9];
    const float* att_b1  = (const float*)d_in[10];
    const float* att_w2  = (const float*)d_in[11];
    const float* att_b2  = (const float*)d_in[12];
    const float* att_w3  = (const float*)d_in[13];
    const float* att_b3  = (const float*)d_in[14];
    const float* att_wo  = (const float*)d_in[15];
    const float* att_bo  = (const float*)d_in[16];
    const float* w_done  = (const float*)d_in[17];
    const float* b_done  = (const float*)d_in[18];
    const float* w_mel   = (const float*)d_in[19];
    const float* b_mel   = (const float*)d_in[20];

    float* out      = (float*)d_out;
    float* out_mel  = out;
    float* out_done = out + (long long)BATCH * TQ * NMELS_R;
    float* out_h    = out_done + (long long)BATCH * TQ * 2;

    float *h, *h2, *ctx, *qin, *kin, *kout, *vout, *big, *peq, *pek;
    cudaGetSymbolAddress((void**)&h,    g_h);
    cudaGetSymbolAddress((void**)&h2,   g_h2);
    cudaGetSymbolAddress((void**)&ctx,  g_ctx);
    cudaGetSymbolAddress((void**)&qin,  g_qin);
    cudaGetSymbolAddress((void**)&kin,  g_kin);
    cudaGetSymbolAddress((void**)&kout, g_kout);
    cudaGetSymbolAddress((void**)&vout, g_vout);
    cudaGetSymbolAddress((void**)&big,  g_big);
    cudaGetSymbolAddress((void**)&peq,  g_peq);
    cudaGetSymbolAddress((void**)&pek,  g_pek);

    // opt-in dynamic smem (54272 B > 48KB static limit)
    cudaFuncSetAttribute(gemm_kernel<A_NORMAL, false, E_RELU>,  cudaFuncAttributeMaxDynamicSharedMemorySize, GSMEM_BYTES);
    cudaFuncSetAttribute(gemm_kernel<A_NORMAL, false, E_BIAS>,  cudaFuncAttributeMaxDynamicSharedMemorySize, GSMEM_BYTES);
    cudaFuncSetAttribute(gemm_kernel<A_CONV,   false, E_BIAS>,  cudaFuncAttributeMaxDynamicSharedMemorySize, GSMEM_BYTES);
    cudaFuncSetAttribute(gemm_kernel<A_NORMAL, true,  E_NONE>,  cudaFuncAttributeMaxDynamicSharedMemorySize, GSMEM_BYTES);
    cudaFuncSetAttribute(gemm_kernel<A_NORMAL, false, E_SCALE>, cudaFuncAttributeMaxDynamicSharedMemorySize, GSMEM_BYTES);
    cudaFuncSetAttribute(gemm_kernel<A_NORMAL, false, E_RESID>, cudaFuncAttributeMaxDynamicSharedMemorySize, GSMEM_BYTES);

    const int M  = BATCH * TQ;    // 32768
    const int Mk = BATCH * TKV;   // 16384
    const float rsqrt_tk = 1.0f / sqrtf((float)TKV);

    posenc_kernel<<<(TQ * EMBED + 255) / 256, 256>>>(peq, TQ, 1.0f);
    posenc_kernel<<<(TKV * EMBED + 255) / 256, 256>>>(pek, TKV, 2.0f);
    addpe_kernel<<<(Mk * EMBED + 255) / 256, 256>>>(keys, pek, kin, TKV);

    gemm_kernel<A_NORMAL, false, E_RELU><<<gemm_grid(M, EMBED, 1), 256, GSMEM_BYTES>>>(
        inputs, w_first, h2, b_first, nullptr,
        M, EMBED, NMELS_R, 0, 0, 0, 0, 0.0f);
    gemm_kernel<A_NORMAL, false, E_RELU><<<gemm_grid(M, EMBED, 1), 256, GSMEM_BYTES>>>(
        h2, fc_w + 0 * EMBED * EMBED, h, fc_b + 0 * EMBED, nullptr,
        M, EMBED, EMBED, 0, 0, 0, 0, 0.0f);
    gemm_kernel<A_NORMAL, false, E_RELU><<<gemm_grid(M, EMBED, 1), 256, GSMEM_BYTES>>>(
        h, fc_w + 1 * EMBED * EMBED, h2, fc_b + 1 * EMBED, nullptr,
        M, EMBED, EMBED, 0, 0, 0, 0, 0.0f);
    gemm_kernel<A_NORMAL, false, E_RELU><<<gemm_grid(M, EMBED, 1), 256, GSMEM_BYTES>>>(
        h2, fc_w + 2 * EMBED * EMBED, h, fc_b + 2 * EMBED, nullptr,
        M, EMBED, EMBED, 0, 0, 0, 0, 0.0f);

    for (int i = 0; i < NLAYERS; i++) {
        const int dil = 1 << i;
        gemm_kernel<A_CONV, false, E_BIAS><<<gemm_grid(M, 512, 1), 256, GSMEM_BYTES>>>(
            h, conv_w + (long long)i * 5 * EMBED * 512, big,
            conv_b + i * 512, nullptr,
            M, 512, 5 * EMBED, 0, 0, 0, dil, 0.0f);
        glu_kernel<<<(M * EMBED + 255) / 256, 256>>>(big, h, qin, peq);

        gemm_kernel<A_NORMAL, false, E_BIAS><<<gemm_grid(M, EMBED, 1), 256, GSMEM_BYTES>>>(
            qin, att_w2 + (long long)i * EMBED * EMBED, h2,
            att_b2 + i * EMBED, nullptr,
            M, EMBED, EMBED, 0, 0, 0, 0, 0.0f);
        gemm_kernel<A_NORMAL, false, E_BIAS><<<gemm_grid(Mk, EMBED, 1), 256, GSMEM_BYTES>>>(
            kin, att_w1 + (long long)i * EMBED * EMBED, kout,
            att_b1 + i * EMBED, nullptr,
            Mk, EMBED, EMBED, 0, 0, 0, 0, 0.0f);
        gemm_kernel<A_NORMAL, false, E_BIAS><<<gemm_grid(Mk, EMBED, 1), 256, GSMEM_BYTES>>>(
            values, att_w3 + (long long)i * EMBED * EMBED, vout,
            att_b3 + i * EMBED, nullptr,
            Mk, EMBED, EMBED, 0, 0, 0, 0, 0.0f);

        gemm_kernel<A_NORMAL, true, E_NONE><<<gemm_grid(TQ, TKV, BATCH), 256, GSMEM_BYTES>>>(
            h2, kout, big, nullptr, nullptr,
            TQ, TKV, EMBED,
            (long long)TQ * EMBED, (long long)TKV * EMBED, (long long)TQ * TKV,
            0, 0.0f);
        softmax_kernel<<<M, 128>>>(big);
        gemm_kernel<A_NORMAL, false, E_SCALE><<<gemm_grid(TQ, EMBED, BATCH), 256, GSMEM_BYTES>>>(
            big, vout, ctx, nullptr, nullptr,
            TQ, EMBED, TKV,
            (long long)TQ * TKV, (long long)TKV * EMBED, (long long)TQ * EMBED,
            0, rsqrt_tk);
        gemm_kernel<A_NORMAL, false, E_RESID><<<gemm_grid(M, EMBED, 1), 256, GSMEM_BYTES>>>(
            ctx, att_wo + (long long)i * EMBED * EMBED, h,
            att_bo + i * EMBED, h,
            M, EMBED, EMBED, 0, 0, 0, 0, 0.0f);
    }

    gemm_kernel<A_NORMAL, false, E_BIAS><<<gemm_grid(M, NMELS_R, 1), 256, GSMEM_BYTES>>>(
        h, w_mel, out_mel, b_mel, nullptr,
        M, NMELS_R, EMBED, 0, 0, 0, 0, 0.0f);
    done_kernel<<<(M + 7) / 8, 256>>>(h, w_done, b_done, out_done);
    cudaMemcpyAsync(out_h, h, sizeof(float) * (size_t)M * EMBED,
                    cudaMemcpyDeviceToDevice);
}